// round 13
// baseline (speedup 1.0000x reference)
#include <cuda_runtime.h>
#include <cuda_bf16.h>
#include <stdint.h>

// Problem constants (fixed by the reference)
#define MAXN 100000
#define MAXE 600000
#define F 128
#define BN_EPS 1e-5f

#define SCAN_BLK 4096
#define NBMAX 32

// ---------------- device scratch (no allocations allowed) ----------------
__device__ __align__(16) float g_h[(size_t)MAXN * F];     // h = x @ W
__device__ __align__(16) float g_agg[(size_t)MAXN * F];   // relu(agg)
__device__ __align__(16) __nv_bfloat16 g_xh[(size_t)MAXN * F];
__device__ __align__(16) __nv_bfloat16 g_xl[(size_t)MAXN * F];
__device__ __align__(16) __nv_bfloat16 g_wh[128 * 256];   // [k][c]: c<128 W, c>=128 W_res
__device__ __align__(16) __nv_bfloat16 g_wl[128 * 256];
__device__ int   g_deg[MAXN + 4];
__device__ int   g_off[MAXN + 4];
__device__ int   g_cur[MAXN];
__device__ int   g_src[MAXE];
__device__ float g_dinv[MAXN];
__device__ int   g_bsum[NBMAX];
__device__ float g_sum[F];
__device__ float g_sumsq[F];
__device__ int   g_is64;

// ---------------- helpers ----------------
__device__ __forceinline__ uint32_t smem_u32(const void* p) {
    uint32_t a;
    asm("{ .reg .u64 t; cvta.to.shared.u64 t, %1; cvt.u32.u64 %0, t; }"
        : "=r"(a) : "l"(p));
    return a;
}
__device__ __forceinline__ void split_bf16(float v, __nv_bfloat16& h, __nv_bfloat16& l) {
    h = __float2bfloat16(v);
    l = __float2bfloat16(v - __bfloat162float(h));
}
__device__ __forceinline__ uint32_t pack_bf162(__nv_bfloat16 a, __nv_bfloat16 b) {
    __nv_bfloat162 p = __halves2bfloat162(a, b);
    return *reinterpret_cast<uint32_t*>(&p);
}
__device__ __forceinline__ void cp16(uint32_t dst, const void* src, int srcsize) {
    asm volatile("cp.async.ca.shared.global [%0], [%1], 16, %2;"
        :: "r"(dst), "l"(src), "r"(srcsize) : "memory");
}
#define CP_COMMIT() asm volatile("cp.async.commit_group;" ::: "memory")
#define CP_WAIT(N)  asm volatile("cp.async.wait_group %0;" :: "n"(N) : "memory")

#define LDMX4(r0, r1, r2, r3, addr) \
    asm volatile("ldmatrix.sync.aligned.m8n8.x4.shared.b16 {%0,%1,%2,%3}, [%4];" \
        : "=r"(r0), "=r"(r1), "=r"(r2), "=r"(r3) : "r"(addr))
#define LDMX4T(r0, r1, r2, r3, addr) \
    asm volatile("ldmatrix.sync.aligned.m8n8.x4.trans.shared.b16 {%0,%1,%2,%3}, [%4];" \
        : "=r"(r0), "=r"(r1), "=r"(r2), "=r"(r3) : "r"(addr))
#define MMA16816(c, a, b0, b1) \
    asm volatile("mma.sync.aligned.m16n8k16.row.col.f32.bf16.bf16.f32 " \
        "{%0,%1,%2,%3}, {%4,%5,%6,%7}, {%8,%9}, {%0,%1,%2,%3};" \
        : "+f"((c)[0]), "+f"((c)[1]), "+f"((c)[2]), "+f"((c)[3]) \
        : "r"((a)[0]), "r"((a)[1]), "r"((a)[2]), "r"((a)[3]), "r"(b0), "r"(b1))

// ---------------- init (+ inline edge dtype detect) ----------------
__global__ void init_kernel(const void* ei, int n) {
    int i = blockIdx.x * blockDim.x + threadIdx.x;
    if (i < n) g_deg[i] = 0;
    if (i < F) { g_sum[i] = 0.f; g_sumsq[i] = 0.f; }
    if (i == 0) {
        const long long* p = (const long long*)ei;
        int ok = 1;
#pragma unroll
        for (int q = 0; q < 16; q++) {
            long long v = p[q];
            if (v < 0 || v >= n) { ok = 0; break; }
        }
        g_is64 = ok;
    }
}

// ---------------- hi/lo bf16 conversion: W+W_res (blocks 0..31), x (rest) --
__global__ void conv_kernel(const float* __restrict__ X,
                            const float* __restrict__ Wm,
                            const float* __restrict__ Wres, int n) {
    const int tid = threadIdx.x;
    const int bid = blockIdx.x;
    if (bid < 32) {
        int idx = bid * 256 + tid;        // 0..8191
        int is_res = idx >> 12;
        int r = idx & 4095;
        int k = r >> 5, c4 = r & 31;
        const float* src = is_res ? Wres : Wm;
        float4 v = *(const float4*)&src[k * 128 + c4 * 4];
        __nv_bfloat16 h0, l0, h1, l1, h2, l2, h3, l3;
        split_bf16(v.x, h0, l0); split_bf16(v.y, h1, l1);
        split_bf16(v.z, h2, l2); split_bf16(v.w, h3, l3);
        int dst = k * 256 + is_res * 128 + c4 * 4;
        *(uint2*)&g_wh[dst] = make_uint2(pack_bf162(h0, h1), pack_bf162(h2, h3));
        *(uint2*)&g_wl[dst] = make_uint2(pack_bf162(l0, l1), pack_bf162(l2, l3));
    } else {
        int idx = (bid - 32) * 256 + tid;
        if (idx < n * 32) {
            float4 v = ((const float4*)X)[idx];
            __nv_bfloat16 h0, l0, h1, l1, h2, l2, h3, l3;
            split_bf16(v.x, h0, l0); split_bf16(v.y, h1, l1);
            split_bf16(v.z, h2, l2); split_bf16(v.w, h3, l3);
            *(uint2*)&g_xh[(size_t)idx * 4] =
                make_uint2(pack_bf162(h0, h1), pack_bf162(h2, h3));
            *(uint2*)&g_xl[(size_t)idx * 4] =
                make_uint2(pack_bf162(l0, l1), pack_bf162(l2, l3));
        }
    }
}

// ---------------- degree histogram over destination (col) ----------------
__global__ void deg_kernel(const void* __restrict__ ei, int E) {
    int e = blockIdx.x * blockDim.x + threadIdx.x;
    if (e < E) {
        int c;
        if (g_is64) c = (int)((const long long*)ei)[E + e];
        else        c = ((const int*)ei)[E + e];
        atomicAdd(&g_deg[c], 1);
    }
}

// ---------------- 3-phase scan ----------------
__global__ void scan1_kernel(int n) {
    __shared__ int wsum[32];
    const int t = threadIdx.x;
    const int lane = t & 31;
    const int w = t >> 5;
    const int idx = blockIdx.x * SCAN_BLK + t * 4;

    int d0 = 0, d1 = 0, d2 = 0, d3 = 0;
    if (idx + 3 < n) {
        int4 dd = *(const int4*)&g_deg[idx];
        d0 = dd.x; d1 = dd.y; d2 = dd.z; d3 = dd.w;
    } else {
        if (idx + 0 < n) d0 = g_deg[idx + 0];
        if (idx + 1 < n) d1 = g_deg[idx + 1];
        if (idx + 2 < n) d2 = g_deg[idx + 2];
        if (idx + 3 < n) d3 = g_deg[idx + 3];
    }
    int s = d0 + d1 + d2 + d3;
    int v = s;
#pragma unroll
    for (int o = 1; o < 32; o <<= 1) {
        int a = __shfl_up_sync(0xffffffffu, v, o);
        if (lane >= o) v += a;
    }
    if (lane == 31) wsum[w] = v;
    __syncthreads();
    if (w == 0) {
        int sv = wsum[lane];
#pragma unroll
        for (int o = 1; o < 32; o <<= 1) {
            int a = __shfl_up_sync(0xffffffffu, sv, o);
            if (lane >= o) sv += a;
        }
        wsum[lane] = sv;
    }
    __syncthreads();
    int excl = (w ? wsum[w - 1] : 0) + v - s;

    if (idx + 3 < n) {
        int4 oo = make_int4(excl, excl + d0, excl + d0 + d1, excl + d0 + d1 + d2);
        *(int4*)&g_off[idx] = oo;
        g_dinv[idx + 0] = rsqrtf((float)(d0 + 1));
        g_dinv[idx + 1] = rsqrtf((float)(d1 + 1));
        g_dinv[idx + 2] = rsqrtf((float)(d2 + 1));
        g_dinv[idx + 3] = rsqrtf((float)(d3 + 1));
    } else {
        int e = excl;
        if (idx + 0 < n) { g_off[idx + 0] = e; g_dinv[idx + 0] = rsqrtf((float)(d0 + 1)); e += d0; }
        if (idx + 1 < n) { g_off[idx + 1] = e; g_dinv[idx + 1] = rsqrtf((float)(d1 + 1)); e += d1; }
        if (idx + 2 < n) { g_off[idx + 2] = e; g_dinv[idx + 2] = rsqrtf((float)(d2 + 1)); e += d2; }
        if (idx + 3 < n) { g_off[idx + 3] = e; g_dinv[idx + 3] = rsqrtf((float)(d3 + 1)); }
    }
    if (t == 0) g_bsum[blockIdx.x] = wsum[31];
}

__global__ void scan2_kernel(int nb) {
    int lane = threadIdx.x;
    int v = (lane < nb) ? g_bsum[lane] : 0;
    int orig = v;
#pragma unroll
    for (int o = 1; o < 32; o <<= 1) {
        int a = __shfl_up_sync(0xffffffffu, v, o);
        if (lane >= o) v += a;
    }
    if (lane < nb) g_bsum[lane] = v - orig;
}

__global__ void scan3_kernel(int n) {
    int i = blockIdx.x * blockDim.x + threadIdx.x;
    if (i < n) {
        int o = g_off[i] + g_bsum[i >> 12];
        g_off[i] = o;
        g_cur[i] = o;
    }
}

// ---------------- CSR fill ----------------
__global__ void fill_kernel(const void* __restrict__ ei, int E) {
    int e = blockIdx.x * blockDim.x + threadIdx.x;
    if (e < E) {
        int r, c;
        if (g_is64) {
            r = (int)((const long long*)ei)[e];
            c = (int)((const long long*)ei)[E + e];
        } else {
            r = ((const int*)ei)[e];
            c = ((const int*)ei)[E + e];
        }
        int p = atomicAdd(&g_cur[c], 1);
        g_src[p] = r;
    }
}

// ---------------- mma.sync bf16 GEMM (one weight half per launch) ---------
// Block: 256 threads (2x4 warps), tile 64 rows x 128 cols.
// half=0: x@W -> g_h.  half=1: x@W_res + b_res -> out.
// Warp tile 32x32. 3-term hi/lo product (rel err ~5e-6). 3-stage cp.async.
#define GM 64
#define LDA2 24      // A smem stride (bf16)
#define LDB3 136     // B smem stride (bf16)

__global__ void __launch_bounds__(256, 2)
gemm_mma_kernel(const float* __restrict__ b_res, float* __restrict__ out,
                int n, int half) {
    __shared__ __align__(16) __nv_bfloat16 sA[3][2][GM * LDA2];   // 18 KB
    __shared__ __align__(16) __nv_bfloat16 sB[3][2][16 * LDB3];   // 25.5 KB

    const int tid = threadIdx.x;
    const int lane = tid & 31;
    const int wid = tid >> 5;
    const int warpM = wid >> 2;          // 0..1
    const int warpN = wid & 3;           // 0..3
    const int block_row = blockIdx.x * GM;

    float acc[2][4][4];
#pragma unroll
    for (int i = 0; i < 2; i++)
#pragma unroll
        for (int j = 0; j < 4; j++)
#pragma unroll
            for (int q = 0; q < 4; q++) acc[i][j][q] = 0.f;

    uint32_t uA[3][2], uB[3][2];
#pragma unroll
    for (int s = 0; s < 3; s++) {
#pragma unroll
        for (int p = 0; p < 2; p++) {
            uA[s][p] = smem_u32(sA[s][p]);
            uB[s][p] = smem_u32(sB[s][p]);
        }
    }

    // ---- cp.async roles ----
    const int apart = tid >> 7;
    const int arow = (tid & 127) >> 1;
    const int aseg = tid & 1;
    const int agr = block_row + arow;
    const __nv_bfloat16* asrc =
        (apart ? g_xl : g_xh) + (size_t)(agr < n ? agr : 0) * F + aseg * 8;
    const int asz = (agr < n) ? 16 : 0;
    const uint32_t adst = (uint32_t)(arow * LDA2 + aseg * 8) * 2;

    const int bkr = tid >> 4;            // 0..15
    const int bsg = tid & 15;            // 0..15
    const __nv_bfloat16* bsrc[2];
    bsrc[0] = g_wh + bkr * 256 + half * 128 + bsg * 8;
    bsrc[1] = g_wl + bkr * 256 + half * 128 + bsg * 8;
    const uint32_t bdst = (uint32_t)(bkr * LDB3 + bsg * 8) * 2;

    uint32_t a_off[2];
#pragma unroll
    for (int mf = 0; mf < 2; mf++)
        a_off[mf] = (uint32_t)((warpM * 32 + mf * 16 + (lane & 15)) * (LDA2 * 2)
                  + (lane >> 4) * 16);
    uint32_t b_off[2];
#pragma unroll
    for (int nf2 = 0; nf2 < 2; nf2++)
        b_off[nf2] = (uint32_t)((lane & 15) * (LDB3 * 2)
                   + (warpN * 32 + nf2 * 16 + (lane >> 4) * 8) * 2);

#define ISSUE(st, kc) do { \
        cp16(uA[st][apart] + adst, asrc + (kc), asz); \
        cp16(uB[st][0] + bdst, bsrc[0] + (size_t)(kc) * 256, 16); \
        cp16(uB[st][1] + bdst, bsrc[1] + (size_t)(kc) * 256, 16); \
        CP_COMMIT(); \
    } while (0)

    ISSUE(0, 0);
    ISSUE(1, 16);

#pragma unroll
    for (int c = 0; c < 8; c++) {
        if (c < 6) {
            ISSUE((c + 2) % 3, (c + 2) * 16);
            CP_WAIT(2);
        } else if (c == 6) {
            CP_WAIT(1);
        } else {
            CP_WAIT(0);
        }
        __syncthreads();
        const int st = c % 3;

        uint32_t ah[2][4], al[2][4];
#pragma unroll
        for (int mf = 0; mf < 2; mf++) {
            LDMX4(ah[mf][0], ah[mf][1], ah[mf][2], ah[mf][3], uA[st][0] + a_off[mf]);
            LDMX4(al[mf][0], al[mf][1], al[mf][2], al[mf][3], uA[st][1] + a_off[mf]);
        }
#pragma unroll
        for (int nf2 = 0; nf2 < 2; nf2++) {
            uint32_t bh[4], bl[4];
            LDMX4T(bh[0], bh[1], bh[2], bh[3], uB[st][0] + b_off[nf2]);
            LDMX4T(bl[0], bl[1], bl[2], bl[3], uB[st][1] + b_off[nf2]);
#pragma unroll
            for (int h2 = 0; h2 < 2; h2++) {
                int nf = nf2 * 2 + h2;
#pragma unroll
                for (int mf = 0; mf < 2; mf++) {
                    MMA16816(acc[mf][nf], ah[mf], bh[h2 * 2], bh[h2 * 2 + 1]);
                    MMA16816(acc[mf][nf], ah[mf], bl[h2 * 2], bl[h2 * 2 + 1]);
                    MMA16816(acc[mf][nf], al[mf], bh[h2 * 2], bh[h2 * 2 + 1]);
                }
            }
        }
        __syncthreads();
    }
#undef ISSUE

    // ---- epilogue ----
    float* dst = half ? out : g_h;
#pragma unroll
    for (int mf = 0; mf < 2; mf++) {
        int gr0 = block_row + warpM * 32 + mf * 16 + (lane >> 2);
#pragma unroll
        for (int nf = 0; nf < 4; nf++) {
            int col = warpN * 32 + nf * 8 + (lane & 3) * 2;
            float bias0 = 0.f, bias1 = 0.f;
            if (half) { bias0 = b_res[col]; bias1 = b_res[col + 1]; }
            if (gr0 < n) {
                float2 o = make_float2(acc[mf][nf][0] + bias0,
                                       acc[mf][nf][1] + bias1);
                *(float2*)&dst[(size_t)gr0 * F + col] = o;
            }
            if (gr0 + 8 < n) {
                float2 o = make_float2(acc[mf][nf][2] + bias0,
                                       acc[mf][nf][3] + bias1);
                *(float2*)&dst[(size_t)(gr0 + 8) * F + col] = o;
            }
        }
    }
}

// ---------------- aggregate (gather) + self-loop + bias + ReLU + BN stats --
__global__ void aggregate_kernel(const float* __restrict__ b, int n) {
    __shared__ float bsum[F];
    __shared__ float bsq[F];
    const int t = threadIdx.x;
    if (t < F) { bsum[t] = 0.f; bsq[t] = 0.f; }
    __syncthreads();

    const int node = (blockIdx.x * blockDim.x + t) >> 5;
    const int lane = t & 31;

    if (node < n) {
        const float4* h4 = (const float4*)g_h;
        float dc = g_dinv[node];
        float dc2 = dc * dc;
        int j = g_off[node];
        int end = j + g_deg[node];

        float4 acc = h4[(size_t)node * 32 + lane];
        float4 bv = ((const float4*)b)[lane];
        acc.x = fmaf(acc.x, dc2, bv.x);
        acc.y = fmaf(acc.y, dc2, bv.y);
        acc.z = fmaf(acc.z, dc2, bv.z);
        acc.w = fmaf(acc.w, dc2, bv.w);

        for (; j + 3 < end; j += 4) {
            int r0 = g_src[j], r1 = g_src[j + 1];
            int r2 = g_src[j + 2], r3 = g_src[j + 3];
            float n0 = dc * g_dinv[r0];
            float n1 = dc * g_dinv[r1];
            float n2 = dc * g_dinv[r2];
            float n3 = dc * g_dinv[r3];
            float4 v0 = h4[(size_t)r0 * 32 + lane];
            float4 v1 = h4[(size_t)r1 * 32 + lane];
            float4 v2 = h4[(size_t)r2 * 32 + lane];
            float4 v3 = h4[(size_t)r3 * 32 + lane];
            acc.x = fmaf(v0.x, n0, acc.x); acc.y = fmaf(v0.y, n0, acc.y);
            acc.z = fmaf(v0.z, n0, acc.z); acc.w = fmaf(v0.w, n0, acc.w);
            acc.x = fmaf(v1.x, n1, acc.x); acc.y = fmaf(v1.y, n1, acc.y);
            acc.z = fmaf(v1.z, n1, acc.z); acc.w = fmaf(v1.w, n1, acc.w);
            acc.x = fmaf(v2.x, n2, acc.x); acc.y = fmaf(v2.y, n2, acc.y);
            acc.z = fmaf(v2.z, n2, acc.z); acc.w = fmaf(v2.w, n2, acc.w);
            acc.x = fmaf(v3.x, n3, acc.x); acc.y = fmaf(v3.y, n3, acc.y);
            acc.z = fmaf(v3.z, n3, acc.z); acc.w = fmaf(v3.w, n3, acc.w);
        }
        for (; j < end; j++) {
            int r = g_src[j];
            float nrm = dc * g_dinv[r];
            float4 v = h4[(size_t)r * 32 + lane];
            acc.x = fmaf(v.x, nrm, acc.x);
            acc.y = fmaf(v.y, nrm, acc.y);
            acc.z = fmaf(v.z, nrm, acc.z);
            acc.w = fmaf(v.w, nrm, acc.w);
        }
        acc.x = fmaxf(acc.x, 0.f);
        acc.y = fmaxf(acc.y, 0.f);
        acc.z = fmaxf(acc.z, 0.f);
        acc.w = fmaxf(acc.w, 0.f);
        ((float4*)g_agg)[(size_t)node * 32 + lane] = acc;

        int f0 = lane * 4;
        atomicAdd(&bsum[f0 + 0], acc.x);
        atomicAdd(&bsum[f0 + 1], acc.y);
        atomicAdd(&bsum[f0 + 2], acc.z);
        atomicAdd(&bsum[f0 + 3], acc.w);
        atomicAdd(&bsq[f0 + 0], acc.x * acc.x);
        atomicAdd(&bsq[f0 + 1], acc.y * acc.y);
        atomicAdd(&bsq[f0 + 2], acc.z * acc.z);
        atomicAdd(&bsq[f0 + 3], acc.w * acc.w);
    }
    __syncthreads();
    if (t < F) {
        atomicAdd(&g_sum[t], bsum[t]);
        atomicAdd(&g_sumsq[t], bsq[t]);
    }
}

// ---------------- final: out += relu(agg)*scale + shift (fused BN fold) ----
__global__ void final_kernel(float* __restrict__ out,
                             const float* __restrict__ gamma,
                             const float* __restrict__ beta, int n) {
    __shared__ float ssc[F];
    __shared__ float ssh[F];
    const int t = threadIdx.x;
    if (t < F) {
        float inv_n = 1.f / (float)n;
        float mean = g_sum[t] * inv_n;
        float var = g_sumsq[t] * inv_n - mean * mean;
        float istd = rsqrtf(var + BN_EPS);
        float sc = gamma[t] * istd;
        ssc[t] = sc;
        ssh[t] = beta[t] - mean * sc;
    }
    __syncthreads();

    int tid = blockIdx.x * blockDim.x + t;
    if (tid >= n * (F / 4)) return;
    int s = tid & 31;
    float4 a = ((const float4*)g_agg)[tid];
    float4 sc = *(const float4*)&ssc[s * 4];
    float4 sh = *(const float4*)&ssh[s * 4];
    float4 o = ((float4*)out)[tid];
    o.x += a.x * sc.x + sh.x;
    o.y += a.y * sc.y + sh.y;
    o.z += a.z * sc.z + sh.z;
    o.w += a.w * sc.w + sh.w;
    ((float4*)out)[tid] = o;
}

// ---------------- launch ----------------------------------------------------
static cudaStream_t s_csr = nullptr;
static cudaEvent_t s_evF = nullptr;    // fork after init
static cudaEvent_t s_evG0 = nullptr;   // W gemm done (stream 0)
static cudaEvent_t s_evFill = nullptr; // CSR fill done (s_csr)
static cudaEvent_t s_evG1 = nullptr;   // W_res gemm done (s_csr)

extern "C" void kernel_launch(void* const* d_in, const int* in_sizes, int n_in,
                              void* d_out, int out_size) {
    const float* x        = (const float*)d_in[0];
    const void*  ei       = d_in[1];
    const float* W        = (const float*)d_in[2];
    const float* b        = (const float*)d_in[3];
    const float* gamma    = (const float*)d_in[4];
    const float* beta     = (const float*)d_in[5];
    const float* W_res    = (const float*)d_in[6];
    const float* b_res    = (const float*)d_in[7];
    float* out            = (float*)d_out;

    const int n = in_sizes[0] / F;
    const int E = in_sizes[1] / 2;
    const int nb = (n + SCAN_BLK - 1) / SCAN_BLK;

    if (s_csr == nullptr) {   // first (non-captured) call only; reused thereafter
        cudaStreamCreateWithFlags(&s_csr, cudaStreamNonBlocking);
        cudaEventCreateWithFlags(&s_evF, cudaEventDisableTiming);
        cudaEventCreateWithFlags(&s_evG0, cudaEventDisableTiming);
        cudaEventCreateWithFlags(&s_evFill, cudaEventDisableTiming);
        cudaEventCreateWithFlags(&s_evG1, cudaEventDisableTiming);
    }

    const int T = 256;
    init_kernel<<<(n + T - 1) / T, T>>>(ei, n);

    // fork CSR branch (needs only init); overlaps conv + gemm0
    cudaEventRecord(s_evF, 0);
    cudaStreamWaitEvent(s_csr, s_evF, 0);
    deg_kernel<<<(E + T - 1) / T, T, 0, s_csr>>>(ei, E);
    scan1_kernel<<<nb, 1024, 0, s_csr>>>(n);
    scan2_kernel<<<1, 32, 0, s_csr>>>(nb);
    scan3_kernel<<<(n + T - 1) / T, T, 0, s_csr>>>(n);
    fill_kernel<<<(E + T - 1) / T, T, 0, s_csr>>>(ei, E);
    cudaEventRecord(s_evFill, s_csr);

    // stream 0: conv, then W-half gemm (critical path to aggregate)
    conv_kernel<<<32 + (n * 32 + T - 1) / T, T>>>(x, W, W_res, n);
    gemm_mma_kernel<<<(n + GM - 1) / GM, 256>>>(b_res, out, n, 0);
    cudaEventRecord(s_evG0, 0);

    // s_csr: AFTER gemm0, run the W_res-half gemm concurrently with aggregate
    cudaStreamWaitEvent(s_csr, s_evG0, 0);
    gemm_mma_kernel<<<(n + GM - 1) / GM, 256, 0, s_csr>>>(b_res, out, n, 1);
    cudaEventRecord(s_evG1, s_csr);

    // aggregate needs g_h (stream 0) + CSR (evFill)
    cudaStreamWaitEvent(0, s_evFill, 0);
    {
        long long work = (long long)n * 32;
        aggregate_kernel<<<(int)((work + T - 1) / T), T>>>(b, n);
    }
    // final needs aggregate (stream 0) + W_res gemm (evG1)
    cudaStreamWaitEvent(0, s_evG1, 0);
    {
        int work = n * (F / 4);
        final_kernel<<<(work + T - 1) / T, T>>>(out, gamma, beta, n);
    }
}

// round 14
// speedup vs baseline: 1.3563x; 1.3563x over previous
#include <cuda_runtime.h>
#include <cuda_bf16.h>
#include <stdint.h>

// Problem constants (fixed by the reference)
#define MAXN 100000
#define MAXE 600000
#define F 128
#define BN_EPS 1e-5f

#define SCAN_BLK 4096
#define NBMAX 32
#define AGG_BLOCKS 592     // 4 per SM; warps grid-stride over nodes

// ---------------- device scratch (no allocations allowed) ----------------
__device__ __align__(16) float g_h[(size_t)MAXN * F];     // h = x @ W
__device__ __align__(16) float g_agg[(size_t)MAXN * F];   // relu(agg)
__device__ __align__(16) __nv_bfloat16 g_xh[(size_t)MAXN * F];
__device__ __align__(16) __nv_bfloat16 g_xl[(size_t)MAXN * F];
__device__ __align__(16) __nv_bfloat16 g_wh[128 * 256];   // [k][c]: c<128 W, c>=128 W_res
__device__ __align__(16) __nv_bfloat16 g_wl[128 * 256];
__device__ int   g_deg[MAXN + 4];
__device__ int   g_off[MAXN + 4];
__device__ int   g_cur[MAXN];
__device__ int   g_src[MAXE];
__device__ float g_dinv[MAXN];
__device__ int   g_bsum[NBMAX];
__device__ float g_sum[F];
__device__ float g_sumsq[F];
__device__ int   g_is64;

// ---------------- helpers ----------------
__device__ __forceinline__ uint32_t smem_u32(const void* p) {
    uint32_t a;
    asm("{ .reg .u64 t; cvta.to.shared.u64 t, %1; cvt.u32.u64 %0, t; }"
        : "=r"(a) : "l"(p));
    return a;
}
__device__ __forceinline__ void split_bf16(float v, __nv_bfloat16& h, __nv_bfloat16& l) {
    h = __float2bfloat16(v);
    l = __float2bfloat16(v - __bfloat162float(h));
}
__device__ __forceinline__ uint32_t pack_bf162(__nv_bfloat16 a, __nv_bfloat16 b) {
    __nv_bfloat162 p = __halves2bfloat162(a, b);
    return *reinterpret_cast<uint32_t*>(&p);
}
__device__ __forceinline__ void cp16(uint32_t dst, const void* src, int srcsize) {
    asm volatile("cp.async.ca.shared.global [%0], [%1], 16, %2;"
        :: "r"(dst), "l"(src), "r"(srcsize) : "memory");
}
#define CP_COMMIT() asm volatile("cp.async.commit_group;" ::: "memory")
#define CP_WAIT(N)  asm volatile("cp.async.wait_group %0;" :: "n"(N) : "memory")

#define LDMX4(r0, r1, r2, r3, addr) \
    asm volatile("ldmatrix.sync.aligned.m8n8.x4.shared.b16 {%0,%1,%2,%3}, [%4];" \
        : "=r"(r0), "=r"(r1), "=r"(r2), "=r"(r3) : "r"(addr))
#define LDMX4T(r0, r1, r2, r3, addr) \
    asm volatile("ldmatrix.sync.aligned.m8n8.x4.trans.shared.b16 {%0,%1,%2,%3}, [%4];" \
        : "=r"(r0), "=r"(r1), "=r"(r2), "=r"(r3) : "r"(addr))
#define MMA16816(c, a, b0, b1) \
    asm volatile("mma.sync.aligned.m16n8k16.row.col.f32.bf16.bf16.f32 " \
        "{%0,%1,%2,%3}, {%4,%5,%6,%7}, {%8,%9}, {%0,%1,%2,%3};" \
        : "+f"((c)[0]), "+f"((c)[1]), "+f"((c)[2]), "+f"((c)[3]) \
        : "r"((a)[0]), "r"((a)[1]), "r"((a)[2]), "r"((a)[3]), "r"(b0), "r"(b1))

// ---------------- init (+ inline edge dtype detect) ----------------
__global__ void init_kernel(const void* ei, int n) {
    int i = blockIdx.x * blockDim.x + threadIdx.x;
    if (i < n) g_deg[i] = 0;
    if (i < F) { g_sum[i] = 0.f; g_sumsq[i] = 0.f; }
    if (i == 0) {
        const long long* p = (const long long*)ei;
        int ok = 1;
#pragma unroll
        for (int q = 0; q < 16; q++) {
            long long v = p[q];
            if (v < 0 || v >= n) { ok = 0; break; }
        }
        g_is64 = ok;
    }
}

// ---------------- hi/lo bf16 conversion: W+W_res (blocks 0..31), x (rest) --
__global__ void conv_kernel(const float* __restrict__ X,
                            const float* __restrict__ Wm,
                            const float* __restrict__ Wres, int n) {
    const int tid = threadIdx.x;
    const int bid = blockIdx.x;
    if (bid < 32) {
        int idx = bid * 256 + tid;        // 0..8191
        int is_res = idx >> 12;
        int r = idx & 4095;
        int k = r >> 5, c4 = r & 31;
        const float* src = is_res ? Wres : Wm;
        float4 v = *(const float4*)&src[k * 128 + c4 * 4];
        __nv_bfloat16 h0, l0, h1, l1, h2, l2, h3, l3;
        split_bf16(v.x, h0, l0); split_bf16(v.y, h1, l1);
        split_bf16(v.z, h2, l2); split_bf16(v.w, h3, l3);
        int dst = k * 256 + is_res * 128 + c4 * 4;
        *(uint2*)&g_wh[dst] = make_uint2(pack_bf162(h0, h1), pack_bf162(h2, h3));
        *(uint2*)&g_wl[dst] = make_uint2(pack_bf162(l0, l1), pack_bf162(l2, l3));
    } else {
        int idx = (bid - 32) * 256 + tid;
        if (idx < n * 32) {
            float4 v = ((const float4*)X)[idx];
            __nv_bfloat16 h0, l0, h1, l1, h2, l2, h3, l3;
            split_bf16(v.x, h0, l0); split_bf16(v.y, h1, l1);
            split_bf16(v.z, h2, l2); split_bf16(v.w, h3, l3);
            *(uint2*)&g_xh[(size_t)idx * 4] =
                make_uint2(pack_bf162(h0, h1), pack_bf162(h2, h3));
            *(uint2*)&g_xl[(size_t)idx * 4] =
                make_uint2(pack_bf162(l0, l1), pack_bf162(l2, l3));
        }
    }
}

// ---------------- degree histogram over destination (col) ----------------
__global__ void deg_kernel(const void* __restrict__ ei, int E) {
    int e = blockIdx.x * blockDim.x + threadIdx.x;
    if (e < E) {
        int c;
        if (g_is64) c = (int)((const long long*)ei)[E + e];
        else        c = ((const int*)ei)[E + e];
        atomicAdd(&g_deg[c], 1);
    }
}

// ---------------- 3-phase scan ----------------
__global__ void scan1_kernel(int n) {
    __shared__ int wsum[32];
    const int t = threadIdx.x;
    const int lane = t & 31;
    const int w = t >> 5;
    const int idx = blockIdx.x * SCAN_BLK + t * 4;

    int d0 = 0, d1 = 0, d2 = 0, d3 = 0;
    if (idx + 3 < n) {
        int4 dd = *(const int4*)&g_deg[idx];
        d0 = dd.x; d1 = dd.y; d2 = dd.z; d3 = dd.w;
    } else {
        if (idx + 0 < n) d0 = g_deg[idx + 0];
        if (idx + 1 < n) d1 = g_deg[idx + 1];
        if (idx + 2 < n) d2 = g_deg[idx + 2];
        if (idx + 3 < n) d3 = g_deg[idx + 3];
    }
    int s = d0 + d1 + d2 + d3;
    int v = s;
#pragma unroll
    for (int o = 1; o < 32; o <<= 1) {
        int a = __shfl_up_sync(0xffffffffu, v, o);
        if (lane >= o) v += a;
    }
    if (lane == 31) wsum[w] = v;
    __syncthreads();
    if (w == 0) {
        int sv = wsum[lane];
#pragma unroll
        for (int o = 1; o < 32; o <<= 1) {
            int a = __shfl_up_sync(0xffffffffu, sv, o);
            if (lane >= o) sv += a;
        }
        wsum[lane] = sv;
    }
    __syncthreads();
    int excl = (w ? wsum[w - 1] : 0) + v - s;

    if (idx + 3 < n) {
        int4 oo = make_int4(excl, excl + d0, excl + d0 + d1, excl + d0 + d1 + d2);
        *(int4*)&g_off[idx] = oo;
        g_dinv[idx + 0] = rsqrtf((float)(d0 + 1));
        g_dinv[idx + 1] = rsqrtf((float)(d1 + 1));
        g_dinv[idx + 2] = rsqrtf((float)(d2 + 1));
        g_dinv[idx + 3] = rsqrtf((float)(d3 + 1));
    } else {
        int e = excl;
        if (idx + 0 < n) { g_off[idx + 0] = e; g_dinv[idx + 0] = rsqrtf((float)(d0 + 1)); e += d0; }
        if (idx + 1 < n) { g_off[idx + 1] = e; g_dinv[idx + 1] = rsqrtf((float)(d1 + 1)); e += d1; }
        if (idx + 2 < n) { g_off[idx + 2] = e; g_dinv[idx + 2] = rsqrtf((float)(d2 + 1)); e += d2; }
        if (idx + 3 < n) { g_off[idx + 3] = e; g_dinv[idx + 3] = rsqrtf((float)(d3 + 1)); }
    }
    if (t == 0) g_bsum[blockIdx.x] = wsum[31];
}

__global__ void scan2_kernel(int nb) {
    int lane = threadIdx.x;
    int v = (lane < nb) ? g_bsum[lane] : 0;
    int orig = v;
#pragma unroll
    for (int o = 1; o < 32; o <<= 1) {
        int a = __shfl_up_sync(0xffffffffu, v, o);
        if (lane >= o) v += a;
    }
    if (lane < nb) g_bsum[lane] = v - orig;
}

__global__ void scan3_kernel(int n) {
    int i = blockIdx.x * blockDim.x + threadIdx.x;
    if (i < n) {
        int o = g_off[i] + g_bsum[i >> 12];
        g_off[i] = o;
        g_cur[i] = o;
    }
}

// ---------------- CSR fill ----------------
__global__ void fill_kernel(const void* __restrict__ ei, int E) {
    int e = blockIdx.x * blockDim.x + threadIdx.x;
    if (e < E) {
        int r, c;
        if (g_is64) {
            r = (int)((const long long*)ei)[e];
            c = (int)((const long long*)ei)[E + e];
        } else {
            r = ((const int*)ei)[e];
            c = ((const int*)ei)[E + e];
        }
        int p = atomicAdd(&g_cur[c], 1);
        g_src[p] = r;
    }
}

// ---------------- mma.sync bf16 GEMM (one weight half per launch) ---------
#define GM 64
#define LDA2 24      // A smem stride (bf16)
#define LDB3 136     // B smem stride (bf16)

__global__ void __launch_bounds__(256, 2)
gemm_mma_kernel(const float* __restrict__ b_res, float* __restrict__ out,
                int n, int half) {
    __shared__ __align__(16) __nv_bfloat16 sA[3][2][GM * LDA2];   // 18 KB
    __shared__ __align__(16) __nv_bfloat16 sB[3][2][16 * LDB3];   // 25.5 KB

    const int tid = threadIdx.x;
    const int lane = tid & 31;
    const int wid = tid >> 5;
    const int warpM = wid >> 2;
    const int warpN = wid & 3;
    const int block_row = blockIdx.x * GM;

    float acc[2][4][4];
#pragma unroll
    for (int i = 0; i < 2; i++)
#pragma unroll
        for (int j = 0; j < 4; j++)
#pragma unroll
            for (int q = 0; q < 4; q++) acc[i][j][q] = 0.f;

    uint32_t uA[3][2], uB[3][2];
#pragma unroll
    for (int s = 0; s < 3; s++) {
#pragma unroll
        for (int p = 0; p < 2; p++) {
            uA[s][p] = smem_u32(sA[s][p]);
            uB[s][p] = smem_u32(sB[s][p]);
        }
    }

    const int apart = tid >> 7;
    const int arow = (tid & 127) >> 1;
    const int aseg = tid & 1;
    const int agr = block_row + arow;
    const __nv_bfloat16* asrc =
        (apart ? g_xl : g_xh) + (size_t)(agr < n ? agr : 0) * F + aseg * 8;
    const int asz = (agr < n) ? 16 : 0;
    const uint32_t adst = (uint32_t)(arow * LDA2 + aseg * 8) * 2;

    const int bkr = tid >> 4;
    const int bsg = tid & 15;
    const __nv_bfloat16* bsrc[2];
    bsrc[0] = g_wh + bkr * 256 + half * 128 + bsg * 8;
    bsrc[1] = g_wl + bkr * 256 + half * 128 + bsg * 8;
    const uint32_t bdst = (uint32_t)(bkr * LDB3 + bsg * 8) * 2;

    uint32_t a_off[2];
#pragma unroll
    for (int mf = 0; mf < 2; mf++)
        a_off[mf] = (uint32_t)((warpM * 32 + mf * 16 + (lane & 15)) * (LDA2 * 2)
                  + (lane >> 4) * 16);
    uint32_t b_off[2];
#pragma unroll
    for (int nf2 = 0; nf2 < 2; nf2++)
        b_off[nf2] = (uint32_t)((lane & 15) * (LDB3 * 2)
                   + (warpN * 32 + nf2 * 16 + (lane >> 4) * 8) * 2);

#define ISSUE(st, kc) do { \
        cp16(uA[st][apart] + adst, asrc + (kc), asz); \
        cp16(uB[st][0] + bdst, bsrc[0] + (size_t)(kc) * 256, 16); \
        cp16(uB[st][1] + bdst, bsrc[1] + (size_t)(kc) * 256, 16); \
        CP_COMMIT(); \
    } while (0)

    ISSUE(0, 0);
    ISSUE(1, 16);

#pragma unroll
    for (int c = 0; c < 8; c++) {
        if (c < 6) {
            ISSUE((c + 2) % 3, (c + 2) * 16);
            CP_WAIT(2);
        } else if (c == 6) {
            CP_WAIT(1);
        } else {
            CP_WAIT(0);
        }
        __syncthreads();
        const int st = c % 3;

        uint32_t ah[2][4], al[2][4];
#pragma unroll
        for (int mf = 0; mf < 2; mf++) {
            LDMX4(ah[mf][0], ah[mf][1], ah[mf][2], ah[mf][3], uA[st][0] + a_off[mf]);
            LDMX4(al[mf][0], al[mf][1], al[mf][2], al[mf][3], uA[st][1] + a_off[mf]);
        }
#pragma unroll
        for (int nf2 = 0; nf2 < 2; nf2++) {
            uint32_t bh[4], bl[4];
            LDMX4T(bh[0], bh[1], bh[2], bh[3], uB[st][0] + b_off[nf2]);
            LDMX4T(bl[0], bl[1], bl[2], bl[3], uB[st][1] + b_off[nf2]);
#pragma unroll
            for (int h2 = 0; h2 < 2; h2++) {
                int nf = nf2 * 2 + h2;
#pragma unroll
                for (int mf = 0; mf < 2; mf++) {
                    MMA16816(acc[mf][nf], ah[mf], bh[h2 * 2], bh[h2 * 2 + 1]);
                    MMA16816(acc[mf][nf], ah[mf], bl[h2 * 2], bl[h2 * 2 + 1]);
                    MMA16816(acc[mf][nf], al[mf], bh[h2 * 2], bh[h2 * 2 + 1]);
                }
            }
        }
        __syncthreads();
    }
#undef ISSUE

    // ---- epilogue ----
    float* dst = half ? out : g_h;
#pragma unroll
    for (int mf = 0; mf < 2; mf++) {
        int gr0 = block_row + warpM * 32 + mf * 16 + (lane >> 2);
#pragma unroll
        for (int nf = 0; nf < 4; nf++) {
            int col = warpN * 32 + nf * 8 + (lane & 3) * 2;
            float bias0 = 0.f, bias1 = 0.f;
            if (half) { bias0 = b_res[col]; bias1 = b_res[col + 1]; }
            if (gr0 < n) {
                float2 o = make_float2(acc[mf][nf][0] + bias0,
                                       acc[mf][nf][1] + bias1);
                *(float2*)&dst[(size_t)gr0 * F + col] = o;
            }
            if (gr0 + 8 < n) {
                float2 o = make_float2(acc[mf][nf][2] + bias0,
                                       acc[mf][nf][3] + bias1);
                *(float2*)&dst[(size_t)(gr0 + 8) * F + col] = o;
            }
        }
    }
}

// ---------------- aggregate: grid-strided warps, register BN stats --------
// Each warp processes ~n/4736 nodes; per-lane sum/sq kept in registers and
// flushed ONCE (smem atomic -> global atomic) instead of per-node.
__global__ void __launch_bounds__(256)
aggregate_kernel(const float* __restrict__ b, int n, int nwarps) {
    __shared__ float bsum[F];
    __shared__ float bsq[F];
    const int t = threadIdx.x;
    if (t < F) { bsum[t] = 0.f; bsq[t] = 0.f; }
    __syncthreads();

    const int gw = (blockIdx.x * blockDim.x + t) >> 5;   // global warp id
    const int lane = t & 31;
    const float4* h4 = (const float4*)g_h;
    const float4 bv = ((const float4*)b)[lane];

    float4 S = make_float4(0.f, 0.f, 0.f, 0.f);
    float4 Q = make_float4(0.f, 0.f, 0.f, 0.f);

    for (int node = gw; node < n; node += nwarps) {
        float dc = g_dinv[node];
        float dc2 = dc * dc;
        int j = g_off[node];
        int end = j + g_deg[node];

        float4 acc = h4[(size_t)node * 32 + lane];
        acc.x = fmaf(acc.x, dc2, bv.x);
        acc.y = fmaf(acc.y, dc2, bv.y);
        acc.z = fmaf(acc.z, dc2, bv.z);
        acc.w = fmaf(acc.w, dc2, bv.w);

        for (; j + 3 < end; j += 4) {
            int r0 = g_src[j], r1 = g_src[j + 1];
            int r2 = g_src[j + 2], r3 = g_src[j + 3];
            float n0 = dc * g_dinv[r0];
            float n1 = dc * g_dinv[r1];
            float n2 = dc * g_dinv[r2];
            float n3 = dc * g_dinv[r3];
            float4 v0 = h4[(size_t)r0 * 32 + lane];
            float4 v1 = h4[(size_t)r1 * 32 + lane];
            float4 v2 = h4[(size_t)r2 * 32 + lane];
            float4 v3 = h4[(size_t)r3 * 32 + lane];
            acc.x = fmaf(v0.x, n0, acc.x); acc.y = fmaf(v0.y, n0, acc.y);
            acc.z = fmaf(v0.z, n0, acc.z); acc.w = fmaf(v0.w, n0, acc.w);
            acc.x = fmaf(v1.x, n1, acc.x); acc.y = fmaf(v1.y, n1, acc.y);
            acc.z = fmaf(v1.z, n1, acc.z); acc.w = fmaf(v1.w, n1, acc.w);
            acc.x = fmaf(v2.x, n2, acc.x); acc.y = fmaf(v2.y, n2, acc.y);
            acc.z = fmaf(v2.z, n2, acc.z); acc.w = fmaf(v2.w, n2, acc.w);
            acc.x = fmaf(v3.x, n3, acc.x); acc.y = fmaf(v3.y, n3, acc.y);
            acc.z = fmaf(v3.z, n3, acc.z); acc.w = fmaf(v3.w, n3, acc.w);
        }
        for (; j < end; j++) {
            int r = g_src[j];
            float nrm = dc * g_dinv[r];
            float4 v = h4[(size_t)r * 32 + lane];
            acc.x = fmaf(v.x, nrm, acc.x);
            acc.y = fmaf(v.y, nrm, acc.y);
            acc.z = fmaf(v.z, nrm, acc.z);
            acc.w = fmaf(v.w, nrm, acc.w);
        }
        acc.x = fmaxf(acc.x, 0.f);
        acc.y = fmaxf(acc.y, 0.f);
        acc.z = fmaxf(acc.z, 0.f);
        acc.w = fmaxf(acc.w, 0.f);
        ((float4*)g_agg)[(size_t)node * 32 + lane] = acc;

        S.x += acc.x; S.y += acc.y; S.z += acc.z; S.w += acc.w;
        Q.x = fmaf(acc.x, acc.x, Q.x);
        Q.y = fmaf(acc.y, acc.y, Q.y);
        Q.z = fmaf(acc.z, acc.z, Q.z);
        Q.w = fmaf(acc.w, acc.w, Q.w);
    }

    // one-time flush: smem atomics (per warp), then global (per block)
    int f0 = lane * 4;
    atomicAdd(&bsum[f0 + 0], S.x);
    atomicAdd(&bsum[f0 + 1], S.y);
    atomicAdd(&bsum[f0 + 2], S.z);
    atomicAdd(&bsum[f0 + 3], S.w);
    atomicAdd(&bsq[f0 + 0], Q.x);
    atomicAdd(&bsq[f0 + 1], Q.y);
    atomicAdd(&bsq[f0 + 2], Q.z);
    atomicAdd(&bsq[f0 + 3], Q.w);
    __syncthreads();
    if (t < F) {
        atomicAdd(&g_sum[t], bsum[t]);
        atomicAdd(&g_sumsq[t], bsq[t]);
    }
}

// ---------------- final: out += relu(agg)*scale + shift (fused BN fold) ----
__global__ void final_kernel(float* __restrict__ out,
                             const float* __restrict__ gamma,
                             const float* __restrict__ beta, int n) {
    __shared__ float ssc[F];
    __shared__ float ssh[F];
    const int t = threadIdx.x;
    if (t < F) {
        float inv_n = 1.f / (float)n;
        float mean = g_sum[t] * inv_n;
        float var = g_sumsq[t] * inv_n - mean * mean;
        float istd = rsqrtf(var + BN_EPS);
        float sc = gamma[t] * istd;
        ssc[t] = sc;
        ssh[t] = beta[t] - mean * sc;
    }
    __syncthreads();

    int tid = blockIdx.x * blockDim.x + t;
    if (tid >= n * (F / 4)) return;
    int s = tid & 31;
    float4 a = ((const float4*)g_agg)[tid];
    float4 sc = *(const float4*)&ssc[s * 4];
    float4 sh = *(const float4*)&ssh[s * 4];
    float4 o = ((float4*)out)[tid];
    o.x += a.x * sc.x + sh.x;
    o.y += a.y * sc.y + sh.y;
    o.z += a.z * sc.z + sh.z;
    o.w += a.w * sc.w + sh.w;
    ((float4*)out)[tid] = o;
}

// ---------------- launch ----------------------------------------------------
static cudaStream_t s_csr = nullptr;
static cudaEvent_t s_evF = nullptr;    // fork after init
static cudaEvent_t s_evG0 = nullptr;   // W gemm done (stream 0)
static cudaEvent_t s_evFill = nullptr; // CSR fill done (s_csr)
static cudaEvent_t s_evG1 = nullptr;   // W_res gemm done (s_csr)

extern "C" void kernel_launch(void* const* d_in, const int* in_sizes, int n_in,
                              void* d_out, int out_size) {
    const float* x        = (const float*)d_in[0];
    const void*  ei       = d_in[1];
    const float* W        = (const float*)d_in[2];
    const float* b        = (const float*)d_in[3];
    const float* gamma    = (const float*)d_in[4];
    const float* beta     = (const float*)d_in[5];
    const float* W_res    = (const float*)d_in[6];
    const float* b_res    = (const float*)d_in[7];
    float* out            = (float*)d_out;

    const int n = in_sizes[0] / F;
    const int E = in_sizes[1] / 2;
    const int nb = (n + SCAN_BLK - 1) / SCAN_BLK;

    if (s_csr == nullptr) {   // first (non-captured) call only; reused thereafter
        cudaStreamCreateWithFlags(&s_csr, cudaStreamNonBlocking);
        cudaEventCreateWithFlags(&s_evF, cudaEventDisableTiming);
        cudaEventCreateWithFlags(&s_evG0, cudaEventDisableTiming);
        cudaEventCreateWithFlags(&s_evFill, cudaEventDisableTiming);
        cudaEventCreateWithFlags(&s_evG1, cudaEventDisableTiming);
    }

    const int T = 256;
    init_kernel<<<(n + T - 1) / T, T>>>(ei, n);

    // fork CSR branch (needs only init); overlaps conv + gemm0
    cudaEventRecord(s_evF, 0);
    cudaStreamWaitEvent(s_csr, s_evF, 0);
    deg_kernel<<<(E + T - 1) / T, T, 0, s_csr>>>(ei, E);
    scan1_kernel<<<nb, 1024, 0, s_csr>>>(n);
    scan2_kernel<<<1, 32, 0, s_csr>>>(nb);
    scan3_kernel<<<(n + T - 1) / T, T, 0, s_csr>>>(n);
    fill_kernel<<<(E + T - 1) / T, T, 0, s_csr>>>(ei, E);
    cudaEventRecord(s_evFill, s_csr);

    // stream 0: conv, then W-half gemm (critical path to aggregate)
    conv_kernel<<<32 + (n * 32 + T - 1) / T, T>>>(x, W, W_res, n);
    gemm_mma_kernel<<<(n + GM - 1) / GM, 256>>>(b_res, out, n, 0);
    cudaEventRecord(s_evG0, 0);

    // s_csr: AFTER gemm0, run W_res-half gemm concurrently with aggregate
    cudaStreamWaitEvent(s_csr, s_evG0, 0);
    gemm_mma_kernel<<<(n + GM - 1) / GM, 256, 0, s_csr>>>(b_res, out, n, 1);
    cudaEventRecord(s_evG1, s_csr);

    // aggregate needs g_h (stream 0) + CSR (evFill)
    cudaStreamWaitEvent(0, s_evFill, 0);
    {
        const int nwarps = AGG_BLOCKS * (T / 32);
        aggregate_kernel<<<AGG_BLOCKS, T>>>(b, n, nwarps);
    }
    // final needs aggregate (stream 0) + W_res gemm (evG1)
    cudaStreamWaitEvent(0, s_evG1, 0);
    {
        int work = n * (F / 4);
        final_kernel<<<(work + T - 1) / T, T>>>(out, gamma, beta, n);
    }
}

// round 16
// speedup vs baseline: 1.4778x; 1.0895x over previous
#include <cuda_runtime.h>
#include <cuda_bf16.h>
#include <stdint.h>

// Problem constants (fixed by the reference)
#define MAXN 100000
#define MAXE 600000
#define F 128
#define BN_EPS 1e-5f

#define SCAN_BLK 4096
#define NBMAX 32
#define AGG_BLOCKS 888     // 6 per SM; warps grid-stride over nodes

// ---------------- device scratch (no allocations allowed) ----------------
__device__ __align__(16) float g_h[(size_t)MAXN * F];     // h = x @ W
__device__ __align__(16) float g_agg[(size_t)MAXN * F];   // relu(agg)
__device__ __align__(16) __nv_bfloat16 g_xh[(size_t)MAXN * F];
__device__ __align__(16) __nv_bfloat16 g_xl[(size_t)MAXN * F];
__device__ __align__(16) __nv_bfloat16 g_wh[128 * 256];   // [k][c]: c<128 W, c>=128 W_res
__device__ __align__(16) __nv_bfloat16 g_wl[128 * 256];
__device__ int   g_deg[MAXN + 4];
__device__ int   g_off[MAXN + 4];
__device__ int   g_cur[MAXN];
__device__ int   g_src[MAXE];
__device__ float g_dinv[MAXN];
__device__ int   g_bsum[NBMAX];
__device__ float g_sum[F];
__device__ float g_sumsq[F];
__device__ int   g_is64;

// ---------------- helpers ----------------
__device__ __forceinline__ uint32_t smem_u32(const void* p) {
    uint32_t a;
    asm("{ .reg .u64 t; cvta.to.shared.u64 t, %1; cvt.u32.u64 %0, t; }"
        : "=r"(a) : "l"(p));
    return a;
}
__device__ __forceinline__ void split_bf16(float v, __nv_bfloat16& h, __nv_bfloat16& l) {
    h = __float2bfloat16(v);
    l = __float2bfloat16(v - __bfloat162float(h));
}
__device__ __forceinline__ uint32_t pack_bf162(__nv_bfloat16 a, __nv_bfloat16 b) {
    __nv_bfloat162 p = __halves2bfloat162(a, b);
    return *reinterpret_cast<uint32_t*>(&p);
}
__device__ __forceinline__ void cp16(uint32_t dst, const void* src, int srcsize) {
    asm volatile("cp.async.ca.shared.global [%0], [%1], 16, %2;"
        :: "r"(dst), "l"(src), "r"(srcsize) : "memory");
}
#define CP_COMMIT() asm volatile("cp.async.commit_group;" ::: "memory")
#define CP_WAIT(N)  asm volatile("cp.async.wait_group %0;" :: "n"(N) : "memory")

#define LDMX4(r0, r1, r2, r3, addr) \
    asm volatile("ldmatrix.sync.aligned.m8n8.x4.shared.b16 {%0,%1,%2,%3}, [%4];" \
        : "=r"(r0), "=r"(r1), "=r"(r2), "=r"(r3) : "r"(addr))
#define LDMX4T(r0, r1, r2, r3, addr) \
    asm volatile("ldmatrix.sync.aligned.m8n8.x4.trans.shared.b16 {%0,%1,%2,%3}, [%4];" \
        : "=r"(r0), "=r"(r1), "=r"(r2), "=r"(r3) : "r"(addr))
#define MMA16816(c, a, b0, b1) \
    asm volatile("mma.sync.aligned.m16n8k16.row.col.f32.bf16.bf16.f32 " \
        "{%0,%1,%2,%3}, {%4,%5,%6,%7}, {%8,%9}, {%0,%1,%2,%3};" \
        : "+f"((c)[0]), "+f"((c)[1]), "+f"((c)[2]), "+f"((c)[3]) \
        : "r"((a)[0]), "r"((a)[1]), "r"((a)[2]), "r"((a)[3]), "r"(b0), "r"(b1))

// ---------------- init (+ inline edge dtype detect) ----------------
__global__ void init_kernel(const void* ei, int n) {
    int i = blockIdx.x * blockDim.x + threadIdx.x;
    if (i < n) g_deg[i] = 0;
    if (i < F) { g_sum[i] = 0.f; g_sumsq[i] = 0.f; }
    if (i == 0) {
        const long long* p = (const long long*)ei;
        int ok = 1;
#pragma unroll
        for (int q = 0; q < 16; q++) {
            long long v = p[q];
            if (v < 0 || v >= n) { ok = 0; break; }
        }
        g_is64 = ok;
    }
}

// ---------------- hi/lo bf16 conversion: W+W_res (blocks 0..31), x (rest) --
__global__ void conv_kernel(const float* __restrict__ X,
                            const float* __restrict__ Wm,
                            const float* __restrict__ Wres, int n) {
    const int tid = threadIdx.x;
    const int bid = blockIdx.x;
    if (bid < 32) {
        int idx = bid * 256 + tid;        // 0..8191
        int is_res = idx >> 12;
        int r = idx & 4095;
        int k = r >> 5, c4 = r & 31;
        const float* src = is_res ? Wres : Wm;
        float4 v = *(const float4*)&src[k * 128 + c4 * 4];
        __nv_bfloat16 h0, l0, h1, l1, h2, l2, h3, l3;
        split_bf16(v.x, h0, l0); split_bf16(v.y, h1, l1);
        split_bf16(v.z, h2, l2); split_bf16(v.w, h3, l3);
        int dst = k * 256 + is_res * 128 + c4 * 4;
        *(uint2*)&g_wh[dst] = make_uint2(pack_bf162(h0, h1), pack_bf162(h2, h3));
        *(uint2*)&g_wl[dst] = make_uint2(pack_bf162(l0, l1), pack_bf162(l2, l3));
    } else {
        int idx = (bid - 32) * 256 + tid;
        if (idx < n * 32) {
            float4 v = ((const float4*)X)[idx];
            __nv_bfloat16 h0, l0, h1, l1, h2, l2, h3, l3;
            split_bf16(v.x, h0, l0); split_bf16(v.y, h1, l1);
            split_bf16(v.z, h2, l2); split_bf16(v.w, h3, l3);
            *(uint2*)&g_xh[(size_t)idx * 4] =
                make_uint2(pack_bf162(h0, h1), pack_bf162(h2, h3));
            *(uint2*)&g_xl[(size_t)idx * 4] =
                make_uint2(pack_bf162(l0, l1), pack_bf162(l2, l3));
        }
    }
}

// ---------------- degree histogram over destination (col) ----------------
__global__ void deg_kernel(const void* __restrict__ ei, int E) {
    int e = blockIdx.x * blockDim.x + threadIdx.x;
    if (e < E) {
        int c;
        if (g_is64) c = (int)((const long long*)ei)[E + e];
        else        c = ((const int*)ei)[E + e];
        atomicAdd(&g_deg[c], 1);
    }
}

// ---------------- 3-phase scan ----------------
__global__ void scan1_kernel(int n) {
    __shared__ int wsum[32];
    const int t = threadIdx.x;
    const int lane = t & 31;
    const int w = t >> 5;
    const int idx = blockIdx.x * SCAN_BLK + t * 4;

    int d0 = 0, d1 = 0, d2 = 0, d3 = 0;
    if (idx + 3 < n) {
        int4 dd = *(const int4*)&g_deg[idx];
        d0 = dd.x; d1 = dd.y; d2 = dd.z; d3 = dd.w;
    } else {
        if (idx + 0 < n) d0 = g_deg[idx + 0];
        if (idx + 1 < n) d1 = g_deg[idx + 1];
        if (idx + 2 < n) d2 = g_deg[idx + 2];
        if (idx + 3 < n) d3 = g_deg[idx + 3];
    }
    int s = d0 + d1 + d2 + d3;
    int v = s;
#pragma unroll
    for (int o = 1; o < 32; o <<= 1) {
        int a = __shfl_up_sync(0xffffffffu, v, o);
        if (lane >= o) v += a;
    }
    if (lane == 31) wsum[w] = v;
    __syncthreads();
    if (w == 0) {
        int sv = wsum[lane];
#pragma unroll
        for (int o = 1; o < 32; o <<= 1) {
            int a = __shfl_up_sync(0xffffffffu, sv, o);
            if (lane >= o) sv += a;
        }
        wsum[lane] = sv;
    }
    __syncthreads();
    int excl = (w ? wsum[w - 1] : 0) + v - s;

    if (idx + 3 < n) {
        int4 oo = make_int4(excl, excl + d0, excl + d0 + d1, excl + d0 + d1 + d2);
        *(int4*)&g_off[idx] = oo;
        g_dinv[idx + 0] = rsqrtf((float)(d0 + 1));
        g_dinv[idx + 1] = rsqrtf((float)(d1 + 1));
        g_dinv[idx + 2] = rsqrtf((float)(d2 + 1));
        g_dinv[idx + 3] = rsqrtf((float)(d3 + 1));
    } else {
        int e = excl;
        if (idx + 0 < n) { g_off[idx + 0] = e; g_dinv[idx + 0] = rsqrtf((float)(d0 + 1)); e += d0; }
        if (idx + 1 < n) { g_off[idx + 1] = e; g_dinv[idx + 1] = rsqrtf((float)(d1 + 1)); e += d1; }
        if (idx + 2 < n) { g_off[idx + 2] = e; g_dinv[idx + 2] = rsqrtf((float)(d2 + 1)); e += d2; }
        if (idx + 3 < n) { g_off[idx + 3] = e; g_dinv[idx + 3] = rsqrtf((float)(d3 + 1)); }
    }
    if (t == 0) g_bsum[blockIdx.x] = wsum[31];
}

__global__ void scan2_kernel(int nb) {
    int lane = threadIdx.x;
    int v = (lane < nb) ? g_bsum[lane] : 0;
    int orig = v;
#pragma unroll
    for (int o = 1; o < 32; o <<= 1) {
        int a = __shfl_up_sync(0xffffffffu, v, o);
        if (lane >= o) v += a;
    }
    if (lane < nb) g_bsum[lane] = v - orig;
}

__global__ void scan3_kernel(int n) {
    int i = blockIdx.x * blockDim.x + threadIdx.x;
    if (i < n) {
        int o = g_off[i] + g_bsum[i >> 12];
        g_off[i] = o;
        g_cur[i] = o;
    }
}

// ---------------- CSR fill ----------------
__global__ void fill_kernel(const void* __restrict__ ei, int E) {
    int e = blockIdx.x * blockDim.x + threadIdx.x;
    if (e < E) {
        int r, c;
        if (g_is64) {
            r = (int)((const long long*)ei)[e];
            c = (int)((const long long*)ei)[E + e];
        } else {
            r = ((const int*)ei)[e];
            c = ((const int*)ei)[E + e];
        }
        int p = atomicAdd(&g_cur[c], 1);
        g_src[p] = r;
    }
}

// ---------------- mma.sync bf16 GEMM (one weight half per launch) ---------
#define GM 64
#define LDA2 24      // A smem stride (bf16)
#define LDB3 136     // B smem stride (bf16)

__global__ void __launch_bounds__(256, 2)
gemm_mma_kernel(const float* __restrict__ b_res, float* __restrict__ out,
                int n, int half) {
    __shared__ __align__(16) __nv_bfloat16 sA[3][2][GM * LDA2];   // 18 KB
    __shared__ __align__(16) __nv_bfloat16 sB[3][2][16 * LDB3];   // 25.5 KB

    const int tid = threadIdx.x;
    const int lane = tid & 31;
    const int wid = tid >> 5;
    const int warpM = wid >> 2;
    const int warpN = wid & 3;
    const int block_row = blockIdx.x * GM;

    float acc[2][4][4];
#pragma unroll
    for (int i = 0; i < 2; i++)
#pragma unroll
        for (int j = 0; j < 4; j++)
#pragma unroll
            for (int q = 0; q < 4; q++) acc[i][j][q] = 0.f;

    uint32_t uA[3][2], uB[3][2];
#pragma unroll
    for (int s = 0; s < 3; s++) {
#pragma unroll
        for (int p = 0; p < 2; p++) {
            uA[s][p] = smem_u32(sA[s][p]);
            uB[s][p] = smem_u32(sB[s][p]);
        }
    }

    const int apart = tid >> 7;
    const int arow = (tid & 127) >> 1;
    const int aseg = tid & 1;
    const int agr = block_row + arow;
    const __nv_bfloat16* asrc =
        (apart ? g_xl : g_xh) + (size_t)(agr < n ? agr : 0) * F + aseg * 8;
    const int asz = (agr < n) ? 16 : 0;
    const uint32_t adst = (uint32_t)(arow * LDA2 + aseg * 8) * 2;

    const int bkr = tid >> 4;
    const int bsg = tid & 15;
    const __nv_bfloat16* bsrc[2];
    bsrc[0] = g_wh + bkr * 256 + half * 128 + bsg * 8;
    bsrc[1] = g_wl + bkr * 256 + half * 128 + bsg * 8;
    const uint32_t bdst = (uint32_t)(bkr * LDB3 + bsg * 8) * 2;

    uint32_t a_off[2];
#pragma unroll
    for (int mf = 0; mf < 2; mf++)
        a_off[mf] = (uint32_t)((warpM * 32 + mf * 16 + (lane & 15)) * (LDA2 * 2)
                  + (lane >> 4) * 16);
    uint32_t b_off[2];
#pragma unroll
    for (int nf2 = 0; nf2 < 2; nf2++)
        b_off[nf2] = (uint32_t)((lane & 15) * (LDB3 * 2)
                   + (warpN * 32 + nf2 * 16 + (lane >> 4) * 8) * 2);

#define ISSUE(st, kc) do { \
        cp16(uA[st][apart] + adst, asrc + (kc), asz); \
        cp16(uB[st][0] + bdst, bsrc[0] + (size_t)(kc) * 256, 16); \
        cp16(uB[st][1] + bdst, bsrc[1] + (size_t)(kc) * 256, 16); \
        CP_COMMIT(); \
    } while (0)

    ISSUE(0, 0);
    ISSUE(1, 16);

#pragma unroll
    for (int c = 0; c < 8; c++) {
        if (c < 6) {
            ISSUE((c + 2) % 3, (c + 2) * 16);
            CP_WAIT(2);
        } else if (c == 6) {
            CP_WAIT(1);
        } else {
            CP_WAIT(0);
        }
        __syncthreads();
        const int st = c % 3;

        uint32_t ah[2][4], al[2][4];
#pragma unroll
        for (int mf = 0; mf < 2; mf++) {
            LDMX4(ah[mf][0], ah[mf][1], ah[mf][2], ah[mf][3], uA[st][0] + a_off[mf]);
            LDMX4(al[mf][0], al[mf][1], al[mf][2], al[mf][3], uA[st][1] + a_off[mf]);
        }
#pragma unroll
        for (int nf2 = 0; nf2 < 2; nf2++) {
            uint32_t bh[4], bl[4];
            LDMX4T(bh[0], bh[1], bh[2], bh[3], uB[st][0] + b_off[nf2]);
            LDMX4T(bl[0], bl[1], bl[2], bl[3], uB[st][1] + b_off[nf2]);
#pragma unroll
            for (int h2 = 0; h2 < 2; h2++) {
                int nf = nf2 * 2 + h2;
#pragma unroll
                for (int mf = 0; mf < 2; mf++) {
                    MMA16816(acc[mf][nf], ah[mf], bh[h2 * 2], bh[h2 * 2 + 1]);
                    MMA16816(acc[mf][nf], ah[mf], bl[h2 * 2], bl[h2 * 2 + 1]);
                    MMA16816(acc[mf][nf], al[mf], bh[h2 * 2], bh[h2 * 2 + 1]);
                }
            }
        }
        __syncthreads();
    }
#undef ISSUE

    // ---- epilogue ----
    // half 0 -> g_h (reused soon by aggregate: normal stores, stays in L2)
    // half 1 -> out (not reused until final: streaming stores, keep L2 for g_h)
#pragma unroll
    for (int mf = 0; mf < 2; mf++) {
        int gr0 = block_row + warpM * 32 + mf * 16 + (lane >> 2);
#pragma unroll
        for (int nf = 0; nf < 4; nf++) {
            int col = warpN * 32 + nf * 8 + (lane & 3) * 2;
            if (half) {
                float bias0 = b_res[col];
                float bias1 = b_res[col + 1];
                if (gr0 < n)
                    __stcs((float2*)&out[(size_t)gr0 * F + col],
                           make_float2(acc[mf][nf][0] + bias0, acc[mf][nf][1] + bias1));
                if (gr0 + 8 < n)
                    __stcs((float2*)&out[(size_t)(gr0 + 8) * F + col],
                           make_float2(acc[mf][nf][2] + bias0, acc[mf][nf][3] + bias1));
            } else {
                if (gr0 < n)
                    *(float2*)&g_h[(size_t)gr0 * F + col] =
                        make_float2(acc[mf][nf][0], acc[mf][nf][1]);
                if (gr0 + 8 < n)
                    *(float2*)&g_h[(size_t)(gr0 + 8) * F + col] =
                        make_float2(acc[mf][nf][2], acc[mf][nf][3]);
            }
        }
    }
}

// ---------------- aggregate: grid-strided warps, register BN stats --------
__global__ void __launch_bounds__(256)
aggregate_kernel(const float* __restrict__ b, int n, int nwarps) {
    __shared__ float bsum[F];
    __shared__ float bsq[F];
    const int t = threadIdx.x;
    if (t < F) { bsum[t] = 0.f; bsq[t] = 0.f; }
    __syncthreads();

    const int gw = (blockIdx.x * blockDim.x + t) >> 5;   // global warp id
    const int lane = t & 31;
    const float4* h4 = (const float4*)g_h;
    const float4 bv = ((const float4*)b)[lane];

    float4 S = make_float4(0.f, 0.f, 0.f, 0.f);
    float4 Q = make_float4(0.f, 0.f, 0.f, 0.f);

    for (int node = gw; node < n; node += nwarps) {
        float dc = g_dinv[node];
        float dc2 = dc * dc;
        int j = g_off[node];
        int end = j + g_deg[node];

        float4 acc = h4[(size_t)node * 32 + lane];
        acc.x = fmaf(acc.x, dc2, bv.x);
        acc.y = fmaf(acc.y, dc2, bv.y);
        acc.z = fmaf(acc.z, dc2, bv.z);
        acc.w = fmaf(acc.w, dc2, bv.w);

        for (; j + 3 < end; j += 4) {
            int r0 = g_src[j], r1 = g_src[j + 1];
            int r2 = g_src[j + 2], r3 = g_src[j + 3];
            float n0 = dc * g_dinv[r0];
            float n1 = dc * g_dinv[r1];
            float n2 = dc * g_dinv[r2];
            float n3 = dc * g_dinv[r3];
            float4 v0 = h4[(size_t)r0 * 32 + lane];
            float4 v1 = h4[(size_t)r1 * 32 + lane];
            float4 v2 = h4[(size_t)r2 * 32 + lane];
            float4 v3 = h4[(size_t)r3 * 32 + lane];
            acc.x = fmaf(v0.x, n0, acc.x); acc.y = fmaf(v0.y, n0, acc.y);
            acc.z = fmaf(v0.z, n0, acc.z); acc.w = fmaf(v0.w, n0, acc.w);
            acc.x = fmaf(v1.x, n1, acc.x); acc.y = fmaf(v1.y, n1, acc.y);
            acc.z = fmaf(v1.z, n1, acc.z); acc.w = fmaf(v1.w, n1, acc.w);
            acc.x = fmaf(v2.x, n2, acc.x); acc.y = fmaf(v2.y, n2, acc.y);
            acc.z = fmaf(v2.z, n2, acc.z); acc.w = fmaf(v2.w, n2, acc.w);
            acc.x = fmaf(v3.x, n3, acc.x); acc.y = fmaf(v3.y, n3, acc.y);
            acc.z = fmaf(v3.z, n3, acc.z); acc.w = fmaf(v3.w, n3, acc.w);
        }
        for (; j < end; j++) {
            int r = g_src[j];
            float nrm = dc * g_dinv[r];
            float4 v = h4[(size_t)r * 32 + lane];
            acc.x = fmaf(v.x, nrm, acc.x);
            acc.y = fmaf(v.y, nrm, acc.y);
            acc.z = fmaf(v.z, nrm, acc.z);
            acc.w = fmaf(v.w, nrm, acc.w);
        }
        acc.x = fmaxf(acc.x, 0.f);
        acc.y = fmaxf(acc.y, 0.f);
        acc.z = fmaxf(acc.z, 0.f);
        acc.w = fmaxf(acc.w, 0.f);
        __stcs(&((float4*)g_agg)[(size_t)node * 32 + lane], acc);  // streaming

        S.x += acc.x; S.y += acc.y; S.z += acc.z; S.w += acc.w;
        Q.x = fmaf(acc.x, acc.x, Q.x);
        Q.y = fmaf(acc.y, acc.y, Q.y);
        Q.z = fmaf(acc.z, acc.z, Q.z);
        Q.w = fmaf(acc.w, acc.w, Q.w);
    }

    // one-time flush: smem atomics (per warp), then global (per block)
    int f0 = lane * 4;
    atomicAdd(&bsum[f0 + 0], S.x);
    atomicAdd(&bsum[f0 + 1], S.y);
    atomicAdd(&bsum[f0 + 2], S.z);
    atomicAdd(&bsum[f0 + 3], S.w);
    atomicAdd(&bsq[f0 + 0], Q.x);
    atomicAdd(&bsq[f0 + 1], Q.y);
    atomicAdd(&bsq[f0 + 2], Q.z);
    atomicAdd(&bsq[f0 + 3], Q.w);
    __syncthreads();
    if (t < F) {
        atomicAdd(&g_sum[t], bsum[t]);
        atomicAdd(&g_sumsq[t], bsq[t]);
    }
}

// ---------------- final: out += relu(agg)*scale + shift (fused BN fold) ----
__global__ void final_kernel(float* __restrict__ out,
                             const float* __restrict__ gamma,
                             const float* __restrict__ beta, int n) {
    __shared__ float ssc[F];
    __shared__ float ssh[F];
    const int t = threadIdx.x;
    if (t < F) {
        float inv_n = 1.f / (float)n;
        float mean = g_sum[t] * inv_n;
        float var = g_sumsq[t] * inv_n - mean * mean;
        float istd = rsqrtf(var + BN_EPS);
        float sc = gamma[t] * istd;
        ssc[t] = sc;
        ssh[t] = beta[t] - mean * sc;
    }
    __syncthreads();

    int tid = blockIdx.x * blockDim.x + t;
    if (tid >= n * (F / 4)) return;
    int s = tid & 31;
    float4 a = __ldcs(&((const float4*)g_agg)[tid]);
    float4 sc = *(const float4*)&ssc[s * 4];
    float4 sh = *(const float4*)&ssh[s * 4];
    float4 o = __ldcs(&((const float4*)out)[tid]);
    o.x += a.x * sc.x + sh.x;
    o.y += a.y * sc.y + sh.y;
    o.z += a.z * sc.z + sh.z;
    o.w += a.w * sc.w + sh.w;
    __stcs(&((float4*)out)[tid], o);
}

// ---------------- launch ----------------------------------------------------
static cudaStream_t s_csr = nullptr;
static cudaEvent_t s_evF = nullptr;    // capture fork (origin stream)
static cudaEvent_t s_evG0 = nullptr;   // W gemm done (stream 0)
static cudaEvent_t s_evFill = nullptr; // CSR fill done (s_csr)
static cudaEvent_t s_evG1 = nullptr;   // W_res gemm done (s_csr)

extern "C" void kernel_launch(void* const* d_in, const int* in_sizes, int n_in,
                              void* d_out, int out_size) {
    const float* x        = (const float*)d_in[0];
    const void*  ei       = d_in[1];
    const float* W        = (const float*)d_in[2];
    const float* b        = (const float*)d_in[3];
    const float* gamma    = (const float*)d_in[4];
    const float* beta     = (const float*)d_in[5];
    const float* W_res    = (const float*)d_in[6];
    const float* b_res    = (const float*)d_in[7];
    float* out            = (float*)d_out;

    const int n = in_sizes[0] / F;
    const int E = in_sizes[1] / 2;
    const int nb = (n + SCAN_BLK - 1) / SCAN_BLK;

    if (s_csr == nullptr) {   // first (non-captured) call only; reused thereafter
        cudaStreamCreateWithFlags(&s_csr, cudaStreamNonBlocking);
        cudaEventCreateWithFlags(&s_evF, cudaEventDisableTiming);
        cudaEventCreateWithFlags(&s_evG0, cudaEventDisableTiming);
        cudaEventCreateWithFlags(&s_evFill, cudaEventDisableTiming);
        cudaEventCreateWithFlags(&s_evG1, cudaEventDisableTiming);
    }

    const int T = 256;

    // fork s_csr from the origin stream FIRST (required for graph capture)
    cudaEventRecord(s_evF, 0);
    cudaStreamWaitEvent(s_csr, s_evF, 0);

    // stream 0: conv (no deps) -> gemm0 -> aggregate -> final
    conv_kernel<<<32 + (n * 32 + T - 1) / T, T>>>(x, W, W_res, n);

    // s_csr: init -> CSR build (independent of conv/gemm0)
    init_kernel<<<(n + T - 1) / T, T, 0, s_csr>>>(ei, n);
    deg_kernel<<<(E + T - 1) / T, T, 0, s_csr>>>(ei, E);
    scan1_kernel<<<nb, 1024, 0, s_csr>>>(n);
    scan2_kernel<<<1, 32, 0, s_csr>>>(nb);
    scan3_kernel<<<(n + T - 1) / T, T, 0, s_csr>>>(n);
    fill_kernel<<<(E + T - 1) / T, T, 0, s_csr>>>(ei, E);
    cudaEventRecord(s_evFill, s_csr);

    gemm_mma_kernel<<<(n + GM - 1) / GM, 256>>>(b_res, out, n, 0);
    cudaEventRecord(s_evG0, 0);

    // s_csr: after gemm0, W_res-half gemm runs concurrently with aggregate
    cudaStreamWaitEvent(s_csr, s_evG0, 0);
    gemm_mma_kernel<<<(n + GM - 1) / GM, 256, 0, s_csr>>>(b_res, out, n, 1);
    cudaEventRecord(s_evG1, s_csr);

    // aggregate needs g_h (stream 0) + CSR (evFill)
    cudaStreamWaitEvent(0, s_evFill, 0);
    {
        const int nwarps = AGG_BLOCKS * (T / 32);
        aggregate_kernel<<<AGG_BLOCKS, T>>>(b, n, nwarps);
    }
    // final needs aggregate (stream 0) + W_res gemm (evG1)
    cudaStreamWaitEvent(0, s_evG1, 0);
    {
        int work = n * (F / 4);
        final_kernel<<<(work + T - 1) / T, T>>>(out, gamma, beta, n);
    }
}

// round 17
// speedup vs baseline: 1.5673x; 1.0606x over previous
#include <cuda_runtime.h>
#include <cuda_bf16.h>
#include <stdint.h>

// Problem constants (fixed by the reference)
#define MAXN 100000
#define MAXE 600000
#define F 128
#define BN_EPS 1e-5f

#define SCAN_BLK 4096
#define NBMAX 32
#define AGG_BLOCKS 888     // 6 per SM; warps grid-stride over nodes

// ---------------- device scratch (no allocations allowed) ----------------
__device__ __align__(16) float g_h[(size_t)MAXN * F];     // h = x @ W
__device__ __align__(16) float g_agg[(size_t)MAXN * F];   // relu(agg)
__device__ __align__(16) __nv_bfloat16 g_wh[128 * 256];   // [k][c]: c<128 W, c>=128 W_res
__device__ __align__(16) __nv_bfloat16 g_wl[128 * 256];
__device__ int   g_deg[MAXN + 4];
__device__ int   g_off[MAXN + 4];
__device__ int   g_cur[MAXN];
__device__ int   g_src[MAXE];
__device__ float g_dinv[MAXN];
__device__ int   g_bsum[NBMAX];
__device__ float g_sum[F];
__device__ float g_sumsq[F];
__device__ int   g_is64;

// ---------------- helpers ----------------
__device__ __forceinline__ uint32_t smem_u32(const void* p) {
    uint32_t a;
    asm("{ .reg .u64 t; cvta.to.shared.u64 t, %1; cvt.u32.u64 %0, t; }"
        : "=r"(a) : "l"(p));
    return a;
}
__device__ __forceinline__ void split_bf16(float v, __nv_bfloat16& h, __nv_bfloat16& l) {
    h = __float2bfloat16(v);
    l = __float2bfloat16(v - __bfloat162float(h));
}
__device__ __forceinline__ uint32_t pack_bf162(__nv_bfloat16 a, __nv_bfloat16 b) {
    __nv_bfloat162 p = __halves2bfloat162(a, b);
    return *reinterpret_cast<uint32_t*>(&p);
}
__device__ __forceinline__ void cp16(uint32_t dst, const void* src, int srcsize) {
    asm volatile("cp.async.ca.shared.global [%0], [%1], 16, %2;"
        :: "r"(dst), "l"(src), "r"(srcsize) : "memory");
}
#define CP_COMMIT() asm volatile("cp.async.commit_group;" ::: "memory")
#define CP_WAIT(N)  asm volatile("cp.async.wait_group %0;" :: "n"(N) : "memory")

#define LDMX4(r0, r1, r2, r3, addr) \
    asm volatile("ldmatrix.sync.aligned.m8n8.x4.shared.b16 {%0,%1,%2,%3}, [%4];" \
        : "=r"(r0), "=r"(r1), "=r"(r2), "=r"(r3) : "r"(addr))
#define LDMX4T(r0, r1, r2, r3, addr) \
    asm volatile("ldmatrix.sync.aligned.m8n8.x4.trans.shared.b16 {%0,%1,%2,%3}, [%4];" \
        : "=r"(r0), "=r"(r1), "=r"(r2), "=r"(r3) : "r"(addr))
#define MMA16816(c, a, b0, b1) \
    asm volatile("mma.sync.aligned.m16n8k16.row.col.f32.bf16.bf16.f32 " \
        "{%0,%1,%2,%3}, {%4,%5,%6,%7}, {%8,%9}, {%0,%1,%2,%3};" \
        : "+f"((c)[0]), "+f"((c)[1]), "+f"((c)[2]), "+f"((c)[3]) \
        : "r"((a)[0]), "r"((a)[1]), "r"((a)[2]), "r"((a)[3]), "r"(b0), "r"(b1))

// ---------------- init (+ inline edge dtype detect) ----------------
__global__ void init_kernel(const void* ei, int n) {
    int i = blockIdx.x * blockDim.x + threadIdx.x;
    if (i < n) g_deg[i] = 0;
    if (i < F) { g_sum[i] = 0.f; g_sumsq[i] = 0.f; }
    if (i == 0) {
        const long long* p = (const long long*)ei;
        int ok = 1;
#pragma unroll
        for (int q = 0; q < 16; q++) {
            long long v = p[q];
            if (v < 0 || v >= n) { ok = 0; break; }
        }
        g_is64 = ok;
    }
}

// ---------------- hi/lo bf16 conversion: W + W_res only (tiny) -------------
__global__ void convw_kernel(const float* __restrict__ Wm,
                             const float* __restrict__ Wres) {
    int idx = blockIdx.x * 256 + threadIdx.x;   // 0..8191
    int is_res = idx >> 12;
    int r = idx & 4095;
    int k = r >> 5, c4 = r & 31;
    const float* src = is_res ? Wres : Wm;
    float4 v = *(const float4*)&src[k * 128 + c4 * 4];
    __nv_bfloat16 h0, l0, h1, l1, h2, l2, h3, l3;
    split_bf16(v.x, h0, l0); split_bf16(v.y, h1, l1);
    split_bf16(v.z, h2, l2); split_bf16(v.w, h3, l3);
    int dst = k * 256 + is_res * 128 + c4 * 4;
    *(uint2*)&g_wh[dst] = make_uint2(pack_bf162(h0, h1), pack_bf162(h2, h3));
    *(uint2*)&g_wl[dst] = make_uint2(pack_bf162(l0, l1), pack_bf162(l2, l3));
}

// ---------------- degree histogram over destination (col) ----------------
__global__ void deg_kernel(const void* __restrict__ ei, int E) {
    int e = blockIdx.x * blockDim.x + threadIdx.x;
    if (e < E) {
        int c;
        if (g_is64) c = (int)((const long long*)ei)[E + e];
        else        c = ((const int*)ei)[E + e];
        atomicAdd(&g_deg[c], 1);
    }
}

// ---------------- 3-phase scan ----------------
__global__ void scan1_kernel(int n) {
    __shared__ int wsum[32];
    const int t = threadIdx.x;
    const int lane = t & 31;
    const int w = t >> 5;
    const int idx = blockIdx.x * SCAN_BLK + t * 4;

    int d0 = 0, d1 = 0, d2 = 0, d3 = 0;
    if (idx + 3 < n) {
        int4 dd = *(const int4*)&g_deg[idx];
        d0 = dd.x; d1 = dd.y; d2 = dd.z; d3 = dd.w;
    } else {
        if (idx + 0 < n) d0 = g_deg[idx + 0];
        if (idx + 1 < n) d1 = g_deg[idx + 1];
        if (idx + 2 < n) d2 = g_deg[idx + 2];
        if (idx + 3 < n) d3 = g_deg[idx + 3];
    }
    int s = d0 + d1 + d2 + d3;
    int v = s;
#pragma unroll
    for (int o = 1; o < 32; o <<= 1) {
        int a = __shfl_up_sync(0xffffffffu, v, o);
        if (lane >= o) v += a;
    }
    if (lane == 31) wsum[w] = v;
    __syncthreads();
    if (w == 0) {
        int sv = wsum[lane];
#pragma unroll
        for (int o = 1; o < 32; o <<= 1) {
            int a = __shfl_up_sync(0xffffffffu, sv, o);
            if (lane >= o) sv += a;
        }
        wsum[lane] = sv;
    }
    __syncthreads();
    int excl = (w ? wsum[w - 1] : 0) + v - s;

    if (idx + 3 < n) {
        int4 oo = make_int4(excl, excl + d0, excl + d0 + d1, excl + d0 + d1 + d2);
        *(int4*)&g_off[idx] = oo;
        g_dinv[idx + 0] = rsqrtf((float)(d0 + 1));
        g_dinv[idx + 1] = rsqrtf((float)(d1 + 1));
        g_dinv[idx + 2] = rsqrtf((float)(d2 + 1));
        g_dinv[idx + 3] = rsqrtf((float)(d3 + 1));
    } else {
        int e = excl;
        if (idx + 0 < n) { g_off[idx + 0] = e; g_dinv[idx + 0] = rsqrtf((float)(d0 + 1)); e += d0; }
        if (idx + 1 < n) { g_off[idx + 1] = e; g_dinv[idx + 1] = rsqrtf((float)(d1 + 1)); e += d1; }
        if (idx + 2 < n) { g_off[idx + 2] = e; g_dinv[idx + 2] = rsqrtf((float)(d2 + 1)); e += d2; }
        if (idx + 3 < n) { g_off[idx + 3] = e; g_dinv[idx + 3] = rsqrtf((float)(d3 + 1)); }
    }
    if (t == 0) g_bsum[blockIdx.x] = wsum[31];
}

__global__ void scan2_kernel(int nb) {
    int lane = threadIdx.x;
    int v = (lane < nb) ? g_bsum[lane] : 0;
    int orig = v;
#pragma unroll
    for (int o = 1; o < 32; o <<= 1) {
        int a = __shfl_up_sync(0xffffffffu, v, o);
        if (lane >= o) v += a;
    }
    if (lane < nb) g_bsum[lane] = v - orig;
}

__global__ void scan3_kernel(int n) {
    int i = blockIdx.x * blockDim.x + threadIdx.x;
    if (i < n) {
        int o = g_off[i] + g_bsum[i >> 12];
        g_off[i] = o;
        g_cur[i] = o;
    }
}

// ---------------- CSR fill ----------------
__global__ void fill_kernel(const void* __restrict__ ei, int E) {
    int e = blockIdx.x * blockDim.x + threadIdx.x;
    if (e < E) {
        int r, c;
        if (g_is64) {
            r = (int)((const long long*)ei)[e];
            c = (int)((const long long*)ei)[E + e];
        } else {
            r = ((const int*)ei)[e];
            c = ((const int*)ei)[E + e];
        }
        int p = atomicAdd(&g_cur[c], 1);
        g_src[p] = r;
    }
}

// ---------------- mma.sync bf16 GEMM with inline x conversion -------------
// Block: 256 threads (2x4 warps), tile 64 rows x 128 cols.
// x loaded fp32 (LDG.128, one-chunk register prefetch), converted hi/lo bf16
// at chunk boundary. B (pre-split W half) via 2-stage cp.async.
// half=0: x@W -> g_h.  half=1: x@W_res + b_res -> out (streaming stores).
#define GM 64
#define LDA2 24      // A smem stride (bf16)
#define LDB3 136     // B smem stride (bf16)

__global__ void __launch_bounds__(256, 2)
gemm_mma_kernel(const float* __restrict__ X, const float* __restrict__ b_res,
                float* __restrict__ out, int n, int half) {
    __shared__ __align__(16) __nv_bfloat16 sA[2][2][GM * LDA2];   // 12 KB
    __shared__ __align__(16) __nv_bfloat16 sB[2][2][16 * LDB3];   // 17 KB

    const int tid = threadIdx.x;
    const int lane = tid & 31;
    const int wid = tid >> 5;
    const int warpM = wid >> 2;
    const int warpN = wid & 3;
    const int block_row = blockIdx.x * GM;

    float acc[2][4][4];
#pragma unroll
    for (int i = 0; i < 2; i++)
#pragma unroll
        for (int j = 0; j < 4; j++)
#pragma unroll
            for (int q = 0; q < 4; q++) acc[i][j][q] = 0.f;

    uint32_t uB[2][2];
#pragma unroll
    for (int s = 0; s < 2; s++) {
        uB[s][0] = smem_u32(sB[s][0]);
        uB[s][1] = smem_u32(sB[s][1]);
    }
    char* sA_b[2][2];
#pragma unroll
    for (int s = 0; s < 2; s++) {
        sA_b[s][0] = (char*)sA[s][0];
        sA_b[s][1] = (char*)sA[s][1];
    }
    uint32_t uA[2][2];
#pragma unroll
    for (int s = 0; s < 2; s++) {
        uA[s][0] = smem_u32(sA[s][0]);
        uA[s][1] = smem_u32(sA[s][1]);
    }

    // ---- A role: one float4 of x per thread per chunk ----
    const int arow = tid >> 2;          // 0..63
    const int akq = tid & 3;            // float4 index in 16-k chunk
    const int agr = block_row + arow;
    const bool avalid = (agr < n);
    const float4* axsrc = (const float4*)(X + (size_t)(avalid ? agr : 0) * F) + akq;
    const uint32_t adst = (uint32_t)(arow * LDA2 + akq * 4) * 2;

    // ---- B role: one 16B seg per part per thread ----
    const int bkr = tid >> 4;
    const int bsg = tid & 15;
    const __nv_bfloat16* bsrc[2];
    bsrc[0] = g_wh + bkr * 256 + half * 128 + bsg * 8;
    bsrc[1] = g_wl + bkr * 256 + half * 128 + bsg * 8;
    const uint32_t bdst = (uint32_t)(bkr * LDB3 + bsg * 8) * 2;

    uint32_t a_off[2];
#pragma unroll
    for (int mf = 0; mf < 2; mf++)
        a_off[mf] = (uint32_t)((warpM * 32 + mf * 16 + (lane & 15)) * (LDA2 * 2)
                  + (lane >> 4) * 16);
    uint32_t b_off[2];
#pragma unroll
    for (int nf2 = 0; nf2 < 2; nf2++)
        b_off[nf2] = (uint32_t)((lane & 15) * (LDB3 * 2)
                   + (warpN * 32 + nf2 * 16 + (lane >> 4) * 8) * 2);

#define ISSUE_B(st, kc) do { \
        cp16(uB[st][0] + bdst, bsrc[0] + (size_t)(kc) * 256, 16); \
        cp16(uB[st][1] + bdst, bsrc[1] + (size_t)(kc) * 256, 16); \
        CP_COMMIT(); \
    } while (0)

    const float4 fz = make_float4(0.f, 0.f, 0.f, 0.f);
    float4 va = avalid ? axsrc[0] : fz;
    ISSUE_B(0, 0);

#pragma unroll
    for (int c = 0; c < 8; c++) {
        const int st = c & 1;
        // convert prefetched x chunk into sA[st]
        {
            __nv_bfloat16 h0, l0, h1, l1, h2, l2, h3, l3;
            split_bf16(va.x, h0, l0); split_bf16(va.y, h1, l1);
            split_bf16(va.z, h2, l2); split_bf16(va.w, h3, l3);
            *(uint2*)(sA_b[st][0] + adst) =
                make_uint2(pack_bf162(h0, h1), pack_bf162(h2, h3));
            *(uint2*)(sA_b[st][1] + adst) =
                make_uint2(pack_bf162(l0, l1), pack_bf162(l2, l3));
        }
        if (c < 7) {
            ISSUE_B((c + 1) & 1, (c + 1) * 16);
            CP_WAIT(1);
        } else {
            CP_WAIT(0);
        }
        __syncthreads();
        // prefetch next x chunk (overlaps compute below)
        if (c < 7) va = avalid ? axsrc[(c + 1) * 4] : fz;

        uint32_t ah[2][4], al[2][4];
#pragma unroll
        for (int mf = 0; mf < 2; mf++) {
            LDMX4(ah[mf][0], ah[mf][1], ah[mf][2], ah[mf][3], uA[st][0] + a_off[mf]);
            LDMX4(al[mf][0], al[mf][1], al[mf][2], al[mf][3], uA[st][1] + a_off[mf]);
        }
#pragma unroll
        for (int nf2 = 0; nf2 < 2; nf2++) {
            uint32_t bh[4], bl[4];
            LDMX4T(bh[0], bh[1], bh[2], bh[3], uB[st][0] + b_off[nf2]);
            LDMX4T(bl[0], bl[1], bl[2], bl[3], uB[st][1] + b_off[nf2]);
#pragma unroll
            for (int h2 = 0; h2 < 2; h2++) {
                int nf = nf2 * 2 + h2;
#pragma unroll
                for (int mf = 0; mf < 2; mf++) {
                    MMA16816(acc[mf][nf], ah[mf], bh[h2 * 2], bh[h2 * 2 + 1]);
                    MMA16816(acc[mf][nf], ah[mf], bl[h2 * 2], bl[h2 * 2 + 1]);
                    MMA16816(acc[mf][nf], al[mf], bh[h2 * 2], bh[h2 * 2 + 1]);
                }
            }
        }
        __syncthreads();
    }
#undef ISSUE_B

    // ---- epilogue ----
#pragma unroll
    for (int mf = 0; mf < 2; mf++) {
        int gr0 = block_row + warpM * 32 + mf * 16 + (lane >> 2);
#pragma unroll
        for (int nf = 0; nf < 4; nf++) {
            int col = warpN * 32 + nf * 8 + (lane & 3) * 2;
            if (half) {
                float bias0 = b_res[col];
                float bias1 = b_res[col + 1];
                if (gr0 < n)
                    __stcs((float2*)&out[(size_t)gr0 * F + col],
                           make_float2(acc[mf][nf][0] + bias0, acc[mf][nf][1] + bias1));
                if (gr0 + 8 < n)
                    __stcs((float2*)&out[(size_t)(gr0 + 8) * F + col],
                           make_float2(acc[mf][nf][2] + bias0, acc[mf][nf][3] + bias1));
            } else {
                if (gr0 < n)
                    *(float2*)&g_h[(size_t)gr0 * F + col] =
                        make_float2(acc[mf][nf][0], acc[mf][nf][1]);
                if (gr0 + 8 < n)
                    *(float2*)&g_h[(size_t)(gr0 + 8) * F + col] =
                        make_float2(acc[mf][nf][2], acc[mf][nf][3]);
            }
        }
    }
}

// ---------------- aggregate: grid-strided warps, register BN stats --------
__global__ void __launch_bounds__(256)
aggregate_kernel(const float* __restrict__ b, int n, int nwarps) {
    __shared__ float bsum[F];
    __shared__ float bsq[F];
    const int t = threadIdx.x;
    if (t < F) { bsum[t] = 0.f; bsq[t] = 0.f; }
    __syncthreads();

    const int gw = (blockIdx.x * blockDim.x + t) >> 5;   // global warp id
    const int lane = t & 31;
    const float4* h4 = (const float4*)g_h;
    const float4 bv = ((const float4*)b)[lane];

    float4 S = make_float4(0.f, 0.f, 0.f, 0.f);
    float4 Q = make_float4(0.f, 0.f, 0.f, 0.f);

    for (int node = gw; node < n; node += nwarps) {
        float dc = g_dinv[node];
        float dc2 = dc * dc;
        int j = g_off[node];
        int end = j + g_deg[node];

        float4 acc = h4[(size_t)node * 32 + lane];
        acc.x = fmaf(acc.x, dc2, bv.x);
        acc.y = fmaf(acc.y, dc2, bv.y);
        acc.z = fmaf(acc.z, dc2, bv.z);
        acc.w = fmaf(acc.w, dc2, bv.w);

        for (; j + 3 < end; j += 4) {
            int r0 = g_src[j], r1 = g_src[j + 1];
            int r2 = g_src[j + 2], r3 = g_src[j + 3];
            float n0 = dc * g_dinv[r0];
            float n1 = dc * g_dinv[r1];
            float n2 = dc * g_dinv[r2];
            float n3 = dc * g_dinv[r3];
            float4 v0 = h4[(size_t)r0 * 32 + lane];
            float4 v1 = h4[(size_t)r1 * 32 + lane];
            float4 v2 = h4[(size_t)r2 * 32 + lane];
            float4 v3 = h4[(size_t)r3 * 32 + lane];
            acc.x = fmaf(v0.x, n0, acc.x); acc.y = fmaf(v0.y, n0, acc.y);
            acc.z = fmaf(v0.z, n0, acc.z); acc.w = fmaf(v0.w, n0, acc.w);
            acc.x = fmaf(v1.x, n1, acc.x); acc.y = fmaf(v1.y, n1, acc.y);
            acc.z = fmaf(v1.z, n1, acc.z); acc.w = fmaf(v1.w, n1, acc.w);
            acc.x = fmaf(v2.x, n2, acc.x); acc.y = fmaf(v2.y, n2, acc.y);
            acc.z = fmaf(v2.z, n2, acc.z); acc.w = fmaf(v2.w, n2, acc.w);
            acc.x = fmaf(v3.x, n3, acc.x); acc.y = fmaf(v3.y, n3, acc.y);
            acc.z = fmaf(v3.z, n3, acc.z); acc.w = fmaf(v3.w, n3, acc.w);
        }
        for (; j < end; j++) {
            int r = g_src[j];
            float nrm = dc * g_dinv[r];
            float4 v = h4[(size_t)r * 32 + lane];
            acc.x = fmaf(v.x, nrm, acc.x);
            acc.y = fmaf(v.y, nrm, acc.y);
            acc.z = fmaf(v.z, nrm, acc.z);
            acc.w = fmaf(v.w, nrm, acc.w);
        }
        acc.x = fmaxf(acc.x, 0.f);
        acc.y = fmaxf(acc.y, 0.f);
        acc.z = fmaxf(acc.z, 0.f);
        acc.w = fmaxf(acc.w, 0.f);
        __stcs(&((float4*)g_agg)[(size_t)node * 32 + lane], acc);  // streaming

        S.x += acc.x; S.y += acc.y; S.z += acc.z; S.w += acc.w;
        Q.x = fmaf(acc.x, acc.x, Q.x);
        Q.y = fmaf(acc.y, acc.y, Q.y);
        Q.z = fmaf(acc.z, acc.z, Q.z);
        Q.w = fmaf(acc.w, acc.w, Q.w);
    }

    int f0 = lane * 4;
    atomicAdd(&bsum[f0 + 0], S.x);
    atomicAdd(&bsum[f0 + 1], S.y);
    atomicAdd(&bsum[f0 + 2], S.z);
    atomicAdd(&bsum[f0 + 3], S.w);
    atomicAdd(&bsq[f0 + 0], Q.x);
    atomicAdd(&bsq[f0 + 1], Q.y);
    atomicAdd(&bsq[f0 + 2], Q.z);
    atomicAdd(&bsq[f0 + 3], Q.w);
    __syncthreads();
    if (t < F) {
        atomicAdd(&g_sum[t], bsum[t]);
        atomicAdd(&g_sumsq[t], bsq[t]);
    }
}

// ---------------- final: out += relu(agg)*scale + shift (fused BN fold) ----
__global__ void final_kernel(float* __restrict__ out,
                             const float* __restrict__ gamma,
                             const float* __restrict__ beta, int n) {
    __shared__ float ssc[F];
    __shared__ float ssh[F];
    const int t = threadIdx.x;
    if (t < F) {
        float inv_n = 1.f / (float)n;
        float mean = g_sum[t] * inv_n;
        float var = g_sumsq[t] * inv_n - mean * mean;
        float istd = rsqrtf(var + BN_EPS);
        float sc = gamma[t] * istd;
        ssc[t] = sc;
        ssh[t] = beta[t] - mean * sc;
    }
    __syncthreads();

    int tid = blockIdx.x * blockDim.x + t;
    if (tid >= n * (F / 4)) return;
    int s = tid & 31;
    float4 a = __ldcs(&((const float4*)g_agg)[tid]);
    float4 sc = *(const float4*)&ssc[s * 4];
    float4 sh = *(const float4*)&ssh[s * 4];
    float4 o = __ldcs(&((const float4*)out)[tid]);
    o.x += a.x * sc.x + sh.x;
    o.y += a.y * sc.y + sh.y;
    o.z += a.z * sc.z + sh.z;
    o.w += a.w * sc.w + sh.w;
    __stcs(&((float4*)out)[tid], o);
}

// ---------------- launch ----------------------------------------------------
static cudaStream_t s_csr = nullptr;
static cudaEvent_t s_evF = nullptr;    // capture fork (origin stream)
static cudaEvent_t s_evG0 = nullptr;   // W gemm done (stream 0)
static cudaEvent_t s_evFill = nullptr; // CSR fill done (s_csr)
static cudaEvent_t s_evG1 = nullptr;   // W_res gemm done (s_csr)

extern "C" void kernel_launch(void* const* d_in, const int* in_sizes, int n_in,
                              void* d_out, int out_size) {
    const float* x        = (const float*)d_in[0];
    const void*  ei       = d_in[1];
    const float* W        = (const float*)d_in[2];
    const float* b        = (const float*)d_in[3];
    const float* gamma    = (const float*)d_in[4];
    const float* beta     = (const float*)d_in[5];
    const float* W_res    = (const float*)d_in[6];
    const float* b_res    = (const float*)d_in[7];
    float* out            = (float*)d_out;

    const int n = in_sizes[0] / F;
    const int E = in_sizes[1] / 2;
    const int nb = (n + SCAN_BLK - 1) / SCAN_BLK;

    if (s_csr == nullptr) {   // first (non-captured) call only; reused thereafter
        cudaStreamCreateWithFlags(&s_csr, cudaStreamNonBlocking);
        cudaEventCreateWithFlags(&s_evF, cudaEventDisableTiming);
        cudaEventCreateWithFlags(&s_evG0, cudaEventDisableTiming);
        cudaEventCreateWithFlags(&s_evFill, cudaEventDisableTiming);
        cudaEventCreateWithFlags(&s_evG1, cudaEventDisableTiming);
    }

    const int T = 256;

    // fork s_csr from the origin stream FIRST (required for graph capture)
    cudaEventRecord(s_evF, 0);
    cudaStreamWaitEvent(s_csr, s_evF, 0);

    // stream 0: tiny W conversion -> gemm0 (x converted inline) -> aggregate -> final
    convw_kernel<<<32, T>>>(W, W_res);

    // s_csr: init -> CSR build (independent of convw/gemm0)
    init_kernel<<<(n + T - 1) / T, T, 0, s_csr>>>(ei, n);
    deg_kernel<<<(E + T - 1) / T, T, 0, s_csr>>>(ei, E);
    scan1_kernel<<<nb, 1024, 0, s_csr>>>(n);
    scan2_kernel<<<1, 32, 0, s_csr>>>(nb);
    scan3_kernel<<<(n + T - 1) / T, T, 0, s_csr>>>(n);
    fill_kernel<<<(E + T - 1) / T, T, 0, s_csr>>>(ei, E);
    cudaEventRecord(s_evFill, s_csr);

    gemm_mma_kernel<<<(n + GM - 1) / GM, 256>>>(x, b_res, out, n, 0);
    cudaEventRecord(s_evG0, 0);

    // s_csr: after gemm0, W_res-half gemm runs concurrently with aggregate
    cudaStreamWaitEvent(s_csr, s_evG0, 0);
    gemm_mma_kernel<<<(n + GM - 1) / GM, 256, 0, s_csr>>>(x, b_res, out, n, 1);
    cudaEventRecord(s_evG1, s_csr);

    // aggregate needs g_h (stream 0) + CSR (evFill)
    cudaStreamWaitEvent(0, s_evFill, 0);
    {
        const int nwarps = AGG_BLOCKS * (T / 32);
        aggregate_kernel<<<AGG_BLOCKS, T>>>(b, n, nwarps);
    }
    // final needs aggregate (stream 0) + W_res gemm (evG1)
    cudaStreamWaitEvent(0, s_evG1, 0);
    {
        int work = n * (F / 4);
        final_kernel<<<(work + T - 1) / T, T>>>(out, gamma, beta, n);
    }
}